// round 13
// baseline (speedup 1.0000x reference)
#include <cuda_runtime.h>
#include <cuda_bf16.h>
#include <math.h>
#include <cstdint>

#define Bv 2
#define Tv 2048
#define Dv 1024
#define Hv 16
#define HDv 64
#define SCv 64
#define STv 16
#define Mrows (Bv*Tv)   // 4096
#define EPSR 1.1920929e-07f
#define CH 64
#define TSTEP (Tv/CH)   // 32
#define ZSPLIT 8

// ---------------- scratch (device globals) ----------------
__device__ __nv_bfloat16 g_h   [Mrows*Dv];
__device__ __nv_bfloat16 g_qk  [Mrows*2*Dv];
__device__ __nv_bfloat16 g_vT  [Dv*Mrows];
__device__ __nv_bfloat16 g_attn[Mrows*Dv];
__device__ float         g_x1  [Mrows*Dv];
__device__ __nv_bfloat16 g_h2  [Mrows*Dv];
__device__ float g_z   [Mrows*SCv];
__device__ float g_gate[Mrows*SCv];
__device__ float g_Bi  [Mrows*STv];
__device__ float g_Ci  [Mrows*STv];
__device__ float g_dt  [Mrows*SCv];
__device__ __nv_bfloat16 g_y [Mrows*SCv];
__device__ float g_scanA[128*CH*16];
__device__ float g_scanB[128*CH*16];
__device__ float g_scanS[128*CH*16];
__device__ float g_zgacc[ZSPLIT*Mrows*128];
__device__ __nv_bfloat16 g_wq  [3*Dv*Dv];
__device__ __nv_bfloat16 g_wo  [Dv*Dv];
__device__ __nv_bfloat16 g_wzg [2*SCv*Dv];
__device__ __nv_bfloat16 g_wout[Dv*SCv];

__device__ __forceinline__ uint32_t packbf(float a, float b) {
    __nv_bfloat162 t = __floats2bfloat162_rn(a, b);
    return *reinterpret_cast<uint32_t*>(&t);
}
__device__ __forceinline__ float ex2(float x) {
    float y;
    asm("ex2.approx.f32 %0, %1;" : "=f"(y) : "f"(x));
    return y;
}
__device__ __forceinline__ uint32_t ex2b2(uint32_t x) {
    uint32_t y;
    asm("ex2.approx.ftz.bf16x2 %0, %1;" : "=r"(y) : "r"(x));
    return y;
}
__device__ __forceinline__ float bf2sum(uint32_t w) {
    float lo = __uint_as_float(w << 16);
    float hi = __uint_as_float(w & 0xffff0000u);
    return lo + hi;
}
__device__ __forceinline__ uint32_t scale_pack(uint32_t w, float s) {
    __nv_bfloat162 t = *reinterpret_cast<__nv_bfloat162*>(&w);
    return packbf(__bfloat162float(t.x)*s, __bfloat162float(t.y)*s);
}

__device__ __forceinline__ void mma_bf16(float& d0, float& d1, float& d2, float& d3,
                                         uint32_t a0, uint32_t a1, uint32_t a2, uint32_t a3,
                                         uint32_t b0, uint32_t b1) {
    asm volatile(
        "mma.sync.aligned.m16n8k16.row.col.f32.bf16.bf16.f32 "
        "{%0,%1,%2,%3}, {%4,%5,%6,%7}, {%8,%9}, {%0,%1,%2,%3};"
        : "+f"(d0), "+f"(d1), "+f"(d2), "+f"(d3)
        : "r"(a0), "r"(a1), "r"(a2), "r"(a3), "r"(b0), "r"(b1));
}

__device__ __forceinline__ void ldsm4(uint32_t& r0, uint32_t& r1, uint32_t& r2, uint32_t& r3,
                                      uint32_t addr) {
    asm volatile("ldmatrix.sync.aligned.m8n8.x4.shared.b16 {%0,%1,%2,%3}, [%4];"
        : "=r"(r0), "=r"(r1), "=r"(r2), "=r"(r3) : "r"(addr));
}

__device__ __forceinline__ void cp16h(__nv_bfloat16* dst, const __nv_bfloat16* src) {
    uint32_t d = (uint32_t)__cvta_generic_to_shared(dst);
    asm volatile("cp.async.cg.shared.global [%0], [%1], 16;" :: "r"(d), "l"(src));
}
#define CP_COMMIT()  asm volatile("cp.async.commit_group;" ::)
#define CP_WAIT2()   asm volatile("cp.async.wait_group 2;" ::)
#define CP_WAIT1()   asm volatile("cp.async.wait_group 1;" ::)
#define CP_WAIT0()   asm volatile("cp.async.wait_group 0;" ::)

// ---------------- merged f32 -> bf16 convert of ALL weights ----------------
#define N2_Q   1572864
#define N2_O   524288
#define N2_S   32768
__global__ __launch_bounds__(256) void conv_all(
    const float* __restrict__ qkv_w, const float* __restrict__ o_w,
    const float* __restrict__ in_w, const float* __restrict__ gate_w,
    const float* __restrict__ out_w)
{
    int i = blockIdx.x*256 + threadIdx.x;
    const float* src; __nv_bfloat162* dst; int j;
    if (i < N2_Q)                        { src = qkv_w;  dst = (__nv_bfloat162*)g_wq;   j = i; }
    else if ((j = i - N2_Q) < N2_O)      { src = o_w;    dst = (__nv_bfloat162*)g_wo; }
    else if ((j = j - N2_O) < N2_S)      { src = in_w;   dst = (__nv_bfloat162*)g_wzg; }
    else if ((j = j - N2_S) < N2_S)      { src = gate_w; dst = (__nv_bfloat162*)g_wzg + N2_S; }
    else if ((j = j - N2_S) < N2_S)      { src = out_w;  dst = (__nv_bfloat162*)g_wout; }
    else return;
    float2 v = ((const float2*)src)[j];
    dst[j] = __floats2bfloat162_rn(v.x, v.y);
}

// ---------------- RMSNorm -> bf16 ----------------
__global__ __launch_bounds__(256) void rmsnorm_kernel(
    const float* __restrict__ x, const float* __restrict__ w, __nv_bfloat16* __restrict__ o)
{
    int row = blockIdx.x;
    const float4* xr = (const float4*)(x + (size_t)row*Dv);
    float4 v = xr[threadIdx.x];
    float ss = v.x*v.x + v.y*v.y + v.z*v.z + v.w*v.w;
    #pragma unroll
    for (int off=16; off; off>>=1) ss += __shfl_xor_sync(0xffffffffu, ss, off);
    __shared__ float sm[8];
    int wid = threadIdx.x>>5, lane = threadIdx.x&31;
    if (lane==0) sm[wid] = ss;
    __syncthreads();
    float tot = sm[0]+sm[1]+sm[2]+sm[3]+sm[4]+sm[5]+sm[6]+sm[7];
    float scale = rsqrtf(tot*(1.0f/Dv) + EPSR);
    const float4* wr = (const float4*)w;
    float4 wv = wr[threadIdx.x];
    uint2 st = make_uint2(packbf(v.x*scale*wv.x, v.y*scale*wv.y),
                          packbf(v.z*scale*wv.z, v.w*scale*wv.w));
    *(uint2*)&o[(size_t)row*Dv + threadIdx.x*4] = st;
}

// ---------------- bf16 GEMM: 3-stage cp.async, split-K capable --------------
// modes: 0 fp32 (with split-K offset); 1 fp32+res; 2 bf16; 3 bf16 transposed; 4 fp32 silu
#define GLDH 40
#define GSTG (128*GLDH)
__global__ __launch_bounds__(256, 2) void gemm_bf16(
    const __nv_bfloat16* __restrict__ A, const __nv_bfloat16* __restrict__ W,
    const float* __restrict__ res, void* __restrict__ Cp, void* __restrict__ C2p,
    int M, int N, int nsplit, int K, int Kstride, int mode1, int mode2, int ld1, int ld2)
{
    extern __shared__ __nv_bfloat16 smg[];
    __nv_bfloat16* Asm = smg;
    __nv_bfloat16* Wsm = smg + 3*GSTG;

    const int tid = threadIdx.x;
    const int w   = tid >> 5;
    const int l   = tid & 31;
    const int g   = l >> 2;
    const int q   = l & 3;
    const int wm  = w >> 1;
    const int wn  = w & 1;
    const int bm  = blockIdx.y * 128;
    const int bn  = blockIdx.x * 128;

    const __nv_bfloat16* Ab = A + (size_t)blockIdx.z * K;
    const __nv_bfloat16* Wb = W + (size_t)blockIdx.z * K;

    const int lr = l & 7, lt = l >> 3;
    const uint32_t sAb = (uint32_t)__cvta_generic_to_shared(Asm);
    const uint32_t sWb = (uint32_t)__cvta_generic_to_shared(Wsm);
    const uint32_t aOff = (uint32_t)((((lt & 1)*8 + lr)*GLDH + (lt >> 1)*8) * 2);
    const uint32_t bOff = (uint32_t)((((lt >> 1)*8 + lr)*GLDH + (lt & 1)*8) * 2);

    const int crow = tid >> 2, cseg = (tid & 3) * 8;

    float c[2][8][4];
    #pragma unroll
    for (int i=0;i<2;i++)
        #pragma unroll
        for (int nj=0;nj<8;nj++)
            #pragma unroll
            for (int e=0;e<4;e++) c[i][nj][e] = 0.f;

    const int nch = K >> 5;

    #pragma unroll
    for (int p = 0; p < 2; p++) {
        #pragma unroll
        for (int ii = 0; ii < 2; ii++) {
            int row = crow + ii*64;
            cp16h(Asm + p*GSTG + row*GLDH + cseg, Ab + (size_t)(bm + row)*Kstride + p*32 + cseg);
            cp16h(Wsm + p*GSTG + row*GLDH + cseg, Wb + (size_t)(bn + row)*Kstride + p*32 + cseg);
        }
        CP_COMMIT();
    }

    for (int i = 0; i < nch; i++) {
        if (i == nch - 1) { CP_WAIT0(); } else { CP_WAIT1(); }
        __syncthreads();
        if (i + 2 < nch) {
            int st = (i + 2) % 3, kn = (i + 2) * 32;
            #pragma unroll
            for (int ii = 0; ii < 2; ii++) {
                int row = crow + ii*64;
                cp16h(Asm + st*GSTG + row*GLDH + cseg, Ab + (size_t)(bm + row)*Kstride + kn + cseg);
                cp16h(Wsm + st*GSTG + row*GLDH + cseg, Wb + (size_t)(bn + row)*Kstride + kn + cseg);
            }
            CP_COMMIT();
        }

        const uint32_t sa = sAb + (uint32_t)((i % 3) * GSTG * 2);
        const uint32_t sw = sWb + (uint32_t)((i % 3) * GSTG * 2);
        #pragma unroll
        for (int kc2 = 0; kc2 < 2; kc2++) {
            uint32_t a[2][4];
            #pragma unroll
            for (int ii = 0; ii < 2; ii++)
                ldsm4(a[ii][0], a[ii][1], a[ii][2], a[ii][3],
                      sa + aOff + (uint32_t)(((wm*32 + ii*16)*GLDH + kc2*16) * 2));
            uint32_t bfr[8][2];
            #pragma unroll
            for (int ncp = 0; ncp < 4; ncp++) {
                uint32_t x0, x1, x2, x3;
                ldsm4(x0, x1, x2, x3,
                      sw + bOff + (uint32_t)(((wn*64 + ncp*16)*GLDH + kc2*16) * 2));
                bfr[2*ncp][0] = x0; bfr[2*ncp][1] = x1;
                bfr[2*ncp+1][0] = x2; bfr[2*ncp+1][1] = x3;
            }
            #pragma unroll
            for (int ii = 0; ii < 2; ii++)
                #pragma unroll
                for (int nj = 0; nj < 8; nj++)
                    mma_bf16(c[ii][nj][0], c[ii][nj][1], c[ii][nj][2], c[ii][nj][3],
                             a[ii][0], a[ii][1], a[ii][2], a[ii][3], bfr[nj][0], bfr[nj][1]);
        }
    }

    #pragma unroll
    for (int i = 0; i < 2; i++) {
        #pragma unroll
        for (int nj = 0; nj < 8; nj++) {
            int row0 = bm + wm*32 + i*16 + g;
            int row1 = row0 + 8;
            int col  = bn + wn*64 + nj*8 + 2*q;
            bool first = (col < nsplit);
            int mode = first ? mode1 : mode2;
            float v0 = c[i][nj][0], v1 = c[i][nj][1], v2 = c[i][nj][2], v3 = c[i][nj][3];
            if (mode == 1) {
                v0 += res[(size_t)row0*N + col];
                v1 += res[(size_t)row0*N + col + 1];
                v2 += res[(size_t)row1*N + col];
                v3 += res[(size_t)row1*N + col + 1];
            } else if (mode == 4) {
                v0 = v0 / (1.f + __expf(-v0));
                v1 = v1 / (1.f + __expf(-v1));
                v2 = v2 / (1.f + __expf(-v2));
                v3 = v3 / (1.f + __expf(-v3));
            }
            if (mode == 2) {
                __nv_bfloat16* O = (__nv_bfloat16*)(first ? Cp : C2p);
                int ld = first ? ld1 : ld2;
                int cc = first ? col : col - nsplit;
                *(uint32_t*)&O[(size_t)row0*ld + cc] = packbf(v0, v1);
                *(uint32_t*)&O[(size_t)row1*ld + cc] = packbf(v2, v3);
            } else if (mode == 3) {
                __nv_bfloat16* O = (__nv_bfloat16*)C2p;
                int cc = col - nsplit;
                O[(size_t)cc*M + row0]     = __float2bfloat16(v0);
                O[(size_t)(cc+1)*M + row0] = __float2bfloat16(v1);
                O[(size_t)cc*M + row1]     = __float2bfloat16(v2);
                O[(size_t)(cc+1)*M + row1] = __float2bfloat16(v3);
            } else {
                float* O = (float*)(first ? Cp : C2p);
                int ld = first ? ld1 : ld2;
                int cc = first ? col : col - nsplit;
                if (mode == 0) O += (size_t)blockIdx.z * M * ld;
                *(float2*)&O[(size_t)row0*ld + cc] = make_float2(v0, v1);
                *(float2*)&O[(size_t)row1*ld + cc] = make_float2(v2, v3);
            }
        }
    }
}

// ---------------- fused split-K reduce + Bi/Ci/dt ----------------
__global__ __launch_bounds__(256) void gemm_bcd(
    const float* __restrict__ Bp_w, const float* __restrict__ Cp_w,
    const float* __restrict__ dt_w, const float* __restrict__ dt_b,
    float* __restrict__ z, float* __restrict__ gate,
    float* __restrict__ Bi, float* __restrict__ Ci, float* __restrict__ dt)
{
    __shared__ float Zs[64*68];
    __shared__ float Wt[64*100];
    const int tid = threadIdx.x;
    const int bm = blockIdx.x*64;

    // reduce z/gate split-K partials for these 64 rows
    for (int t = tid; t < 8192; t += 256) {
        int row = t >> 7, col = t & 127;
        float s = 0.f;
        #pragma unroll
        for (int p = 0; p < ZSPLIT; p++)
            s += g_zgacc[(size_t)p*Mrows*128 + (size_t)(bm + row)*128 + col];
        if (col < SCv) {
            Zs[row*68 + col] = s;
            z[(size_t)(bm + row)*SCv + col] = s;
        } else {
            gate[(size_t)(bm + row)*SCv + col - SCv] = s / (1.f + __expf(-s));
        }
    }
    for (int idx = tid; idx < 96*64; idx += 256) {
        int r = idx >> 6, c = idx & 63;
        float v = (r < 16) ? Bp_w[r*SCv + c] : (r < 32) ? Cp_w[(r-16)*SCv + c] : dt_w[(r-32)*SCv + c];
        Wt[c*100 + r] = v;
    }
    __syncthreads();

    const int ty = tid >> 4, tx = tid & 15;
    float acc[4][6];
    #pragma unroll
    for (int i=0;i<4;i++)
        #pragma unroll
        for (int j=0;j<6;j++) acc[i][j] = 0.f;

    #pragma unroll 4
    for (int k = 0; k < 64; k++) {
        float a[4], bb[6];
        #pragma unroll
        for (int i=0;i<4;i++) a[i] = Zs[(ty*4+i)*68 + k];
        #pragma unroll
        for (int j=0;j<6;j++) bb[j] = Wt[k*100 + tx*6 + j];
        #pragma unroll
        for (int i=0;i<4;i++)
            #pragma unroll
            for (int j=0;j<6;j++) acc[i][j] = fmaf(a[i], bb[j], acc[i][j]);
    }

    #pragma unroll
    for (int i=0;i<4;i++) {
        int row = bm + ty*4 + i;
        #pragma unroll
        for (int j=0;j<6;j++) {
            int c = tx*6 + j;
            float v = acc[i][j];
            if (c < 16) {
                Bi[(size_t)row*STv + c] = v;
            } else if (c < 32) {
                Ci[(size_t)row*STv + (c-16)] = v;
            } else {
                v += dt_b[c-32];
                dt[(size_t)row*SCv + (c-32)] = (v > 20.f) ? v : log1pf(__expf(v));
            }
        }
    }
}

// ---------------- Flash attention v8: 6-stage, sync every 2 tiles ----------
#define KS_LDH 72
#define STAGEH (64*KS_LDH*2)
__global__ __launch_bounds__(256, 2) void attn_mma_kernel(
    const __nv_bfloat16* __restrict__ qk, const __nv_bfloat16* __restrict__ vT,
    __nv_bfloat16* __restrict__ out)
{
    extern __shared__ __nv_bfloat16 smh[];

    const int tid = threadIdx.x;
    const int w   = tid >> 5;
    const int l   = tid & 31;
    const int g   = l >> 2;
    const int q   = l & 3;
    const int qb  = (int)gridDim.x - 1 - (int)blockIdx.x;
    const int h = blockIdx.y, b = blockIdx.z;
    const int qrow0 = qb*128 + w*16;

    const int lr = l & 7, lt = l >> 3;
    const uint32_t smbase = (uint32_t)__cvta_generic_to_shared(smh);
    const uint32_t bOff = (uint32_t)((((lt >> 1)*8 + lr)*KS_LDH + (lt & 1)*8) * 2);

    const float QSC = 0.125f * 1.4426950408889634f;
    uint32_t qa[4][4];
    {
        const uint32_t* Qw0 = (const uint32_t*)(qk + ((size_t)(b*Tv + qrow0 + g    ))*(2*Dv) + h*HDv);
        const uint32_t* Qw1 = (const uint32_t*)(qk + ((size_t)(b*Tv + qrow0 + g + 8))*(2*Dv) + h*HDv);
        #pragma unroll
        for (int kc = 0; kc < 4; kc++) {
            qa[kc][0] = scale_pack(Qw0[kc*8 + q    ], QSC);
            qa[kc][1] = scale_pack(Qw1[kc*8 + q    ], QSC);
            qa[kc][2] = scale_pack(Qw0[kc*8 + q + 4], QSC);
            qa[kc][3] = scale_pack(Qw1[kc*8 + q + 4], QSC);
        }
    }

    float o[8][4];
    #pragma unroll
    for (int nc = 0; nc < 8; nc++)
        #pragma unroll
        for (int e = 0; e < 4; e++) o[nc][e] = 0.f;
    float mA = -1e30f, mB = -1e30f, lA = 0.f, lB = 0.f;

    const int ntiles = 2*qb + 2;   // always even, >= 2

    // prologue: issue tiles 0..3 (empty commits for nonexistent tiles)
    #pragma unroll
    for (int p = 0; p < 4; p++) {
        if (p < ntiles) {
            __nv_bfloat16* Kb = smh + p*STAGEH;
            __nv_bfloat16* Vb = Kb + 64*KS_LDH;
            #pragma unroll
            for (int i = 0; i < 2; i++) {
                int idx = tid + i*256;
                int r = idx >> 3, seg = (idx & 7) * 8;
                cp16h(Kb + r*KS_LDH + seg, qk + ((size_t)(b*Tv + p*64 + r))*(2*Dv) + Dv + h*HDv + seg);
                cp16h(Vb + r*KS_LDH + seg, vT + ((size_t)(h*HDv + r))*Mrows + b*Tv + p*64 + seg);
            }
        }
        CP_COMMIT();
    }

    for (int kt = 0; kt < ntiles; kt += 2) {
        CP_WAIT2();            // tiles kt, kt+1 complete
        __syncthreads();       // all warps done with stages being overwritten below
        #pragma unroll
        for (int pp = 0; pp < 2; pp++) {
            int t = kt + 4 + pp;
            if (t < ntiles) {
                int st = t % 6;
                __nv_bfloat16* Kb = smh + st*STAGEH;
                __nv_bfloat16* Vb = Kb + 64*KS_LDH;
                #pragma unroll
                for (int i = 0; i < 2; i++) {
                    int idx = tid + i*256;
                    int r = idx >> 3, seg = (idx & 7) * 8;
                    cp16h(Kb + r*KS_LDH + seg, qk + ((size_t)(b*Tv + t*64 + r))*(2*Dv) + Dv + h*HDv + seg);
                    cp16h(Vb + r*KS_LDH + seg, vT + ((size_t)(h*HDv + r))*Mrows + b*Tv + t*64 + seg);
                }
            }
            CP_COMMIT();
        }

        #pragma unroll
        for (int sub = 0; sub < 2; sub++) {
            const int kti = kt + sub;
            const int kbase = kti*64;
            const uint32_t kst = smbase + (uint32_t)(((kti % 6)*STAGEH) * 2);
            const uint32_t vst = kst + (uint32_t)(64*KS_LDH*2);

            // ---- S = Q @ K^T via ldmatrix ----
            float s[8][4];
            #pragma unroll
            for (int nc = 0; nc < 8; nc++) {
                s[nc][0] = 0.f; s[nc][1] = 0.f; s[nc][2] = 0.f; s[nc][3] = 0.f;
            }
            #pragma unroll
            for (int ncp = 0; ncp < 4; ncp++) {
                #pragma unroll
                for (int kc = 0; kc < 4; kc++) {
                    uint32_t b0, b1, b2, b3;
                    ldsm4(b0, b1, b2, b3, kst + bOff + (uint32_t)(((ncp*16)*KS_LDH + kc*16) * 2));
                    mma_bf16(s[2*ncp][0], s[2*ncp][1], s[2*ncp][2], s[2*ncp][3],
                             qa[kc][0], qa[kc][1], qa[kc][2], qa[kc][3], b0, b1);
                    mma_bf16(s[2*ncp+1][0], s[2*ncp+1][1], s[2*ncp+1][2], s[2*ncp+1][3],
                             qa[kc][0], qa[kc][1], qa[kc][2], qa[kc][3], b2, b3);
                }
            }

            // ---- causal mask ----
            if (kbase + 63 > qrow0) {
                int rowA = qrow0 + g, rowB = qrow0 + g + 8;
                #pragma unroll
                for (int nc = 0; nc < 8; nc++) {
                    int c0 = kbase + nc*8 + 2*q, c1 = c0 + 1;
                    if (c0 > rowA) s[nc][0] = -1e30f;
                    if (c1 > rowA) s[nc][1] = -1e30f;
                    if (c0 > rowB) s[nc][2] = -1e30f;
                    if (c1 > rowB) s[nc][3] = -1e30f;
                }
            }

            // ---- max + corr ----
            float rmA = -1e30f, rmB = -1e30f;
            #pragma unroll
            for (int nc = 0; nc < 8; nc++) {
                rmA = fmaxf(rmA, fmaxf(s[nc][0], s[nc][1]));
                rmB = fmaxf(rmB, fmaxf(s[nc][2], s[nc][3]));
            }
            rmA = fmaxf(rmA, __shfl_xor_sync(0xffffffffu, rmA, 1));
            rmA = fmaxf(rmA, __shfl_xor_sync(0xffffffffu, rmA, 2));
            rmB = fmaxf(rmB, __shfl_xor_sync(0xffffffffu, rmB, 1));
            rmB = fmaxf(rmB, __shfl_xor_sync(0xffffffffu, rmB, 2));
            float mnA = fmaxf(mA, rmA), mnB = fmaxf(mB, rmB);
            float corrA = ex2(mA - mnA), corrB = ex2(mB - mnB);
            mA = mnA; mB = mnB;

            // ---- P = 2^(s-m) via bf16x2 ex2 (already packed A-frags) ----
            uint32_t pa[4][4];
            #pragma unroll
            for (int kc = 0; kc < 4; kc++) {
                pa[kc][0] = ex2b2(packbf(s[2*kc][0]   - mnA, s[2*kc][1]   - mnA));
                pa[kc][1] = ex2b2(packbf(s[2*kc][2]   - mnB, s[2*kc][3]   - mnB));
                pa[kc][2] = ex2b2(packbf(s[2*kc+1][0] - mnA, s[2*kc+1][1] - mnA));
                pa[kc][3] = ex2b2(packbf(s[2*kc+1][2] - mnB, s[2*kc+1][3] - mnB));
            }

            // ---- rescale O, then issue PV immediately ----
            #pragma unroll
            for (int nc = 0; nc < 8; nc++) {
                o[nc][0] *= corrA; o[nc][1] *= corrA;
                o[nc][2] *= corrB; o[nc][3] *= corrB;
            }
            #pragma unroll
            for (int ncp = 0; ncp < 4; ncp++) {
                #pragma unroll
                for (int kc = 0; kc < 4; kc++) {
                    uint32_t v0, v1, v2, v3;
                    ldsm4(v0, v1, v2, v3, vst + bOff + (uint32_t)(((ncp*16)*KS_LDH + kc*16) * 2));
                    mma_bf16(o[2*ncp][0], o[2*ncp][1], o[2*ncp][2], o[2*ncp][3],
                             pa[kc][0], pa[kc][1], pa[kc][2], pa[kc][3], v0, v1);
                    mma_bf16(o[2*ncp+1][0], o[2*ncp+1][1], o[2*ncp+1][2], o[2*ncp+1][3],
                             pa[kc][0], pa[kc][1], pa[kc][2], pa[kc][3], v2, v3);
                }
            }

            // ---- deferred row-sum (overlaps PV HMMA) ----
            float rsA = 0.f, rsB = 0.f;
            #pragma unroll
            for (int kc = 0; kc < 4; kc++) {
                rsA += bf2sum(pa[kc][0]) + bf2sum(pa[kc][2]);
                rsB += bf2sum(pa[kc][1]) + bf2sum(pa[kc][3]);
            }
            rsA += __shfl_xor_sync(0xffffffffu, rsA, 1);
            rsA += __shfl_xor_sync(0xffffffffu, rsA, 2);
            rsB += __shfl_xor_sync(0xffffffffu, rsB, 1);
            rsB += __shfl_xor_sync(0xffffffffu, rsB, 2);
            lA = lA*corrA + rsA;
            lB = lB*corrB + rsB;
        }
    }

    // ---- write O / l (bf16) ----
    float invA = 1.f / lA, invB = 1.f / lB;
    __nv_bfloat16* ob0 = out + ((size_t)(b*Tv + qrow0 + g    ))*Dv + h*HDv;
    __nv_bfloat16* ob1 = out + ((size_t)(b*Tv + qrow0 + g + 8))*Dv + h*HDv;
    #pragma unroll
    for (int nc = 0; nc < 8; nc++) {
        int c = nc*8 + 2*q;
        *(uint32_t*)&ob0[c] = packbf(o[nc][0]*invA, o[nc][1]*invA);
        *(uint32_t*)&ob1[c] = packbf(o[nc][2]*invB, o[nc][3]*invB);
    }
}

// ---------------- Parallel selective scan (CH=64) ----------------
__global__ __launch_bounds__(256) void scan_phase1(
    const float* __restrict__ dt, const float* __restrict__ z,
    const float* __restrict__ Bi, const float* __restrict__ A_log)
{
    int gth = blockIdx.x*256 + threadIdx.x;
    int chan = gth & 127, chunk = gth >> 7;
    int b = chan >> 6, sc = chan & 63;
    float A[16];
    #pragma unroll
    for (int st = 0; st < 16; st++) A[st] = -__expf(A_log[sc*STv + st]);
    float aP[16], bP[16];
    #pragma unroll
    for (int st = 0; st < 16; st++) { aP[st] = 1.f; bP[st] = 0.f; }
    int t0 = chunk*TSTEP;
    const float* dtp = dt + ((size_t)b*Tv + t0)*SCv + sc;
    const float* zp  = z  + ((size_t)b*Tv + t0)*SCv + sc;
    const float* Bp  = Bi + ((size_t)b*Tv + t0)*STv;
    for (int tt = 0; tt < TSTEP; tt++) {
        float dtc = dtp[(size_t)tt*SCv];
        float zc  = zp [(size_t)tt*SCv];
        float dz  = dtc*zc;
        float4 B0 = *(const float4*)&Bp[tt*STv + 0];
        float4 B1 = *(const float4*)&Bp[tt*STv + 4];
        float4 B2 = *(const float4*)&Bp[tt*STv + 8];
        float4 B3 = *(const float4*)&Bp[tt*STv + 12];
        float Bvv[16] = {B0.x,B0.y,B0.z,B0.w, B1.x,B1.y,B1.z,B1.w,
                         B2.x,B2.y,B2.z,B2.w, B3.x,B3.y,B3.z,B3.w};
        #pragma unroll
        for (int st = 0; st < 16; st++) {
            float ab = fmaf(dtc, A[st], 1.f);
            aP[st] *= ab;
            bP[st] = fmaf(ab, bP[st], dz*Bvv[st]);
        }
    }
    int base = (chan*CH + chunk)*16;
    #pragma unroll
    for (int st = 0; st < 16; st++) { g_scanA[base+st] = aP[st]; g_scanB[base+st] = bP[st]; }
}

__global__ __launch_bounds__(256) void scan_phase2()
{
    int gth = blockIdx.x*256 + threadIdx.x;
    int chan = gth >> 4, st = gth & 15;
    float s = 0.f;
    #pragma unroll 8
    for (int ch = 0; ch < CH; ch++) {
        int idx = (chan*CH + ch)*16 + st;
        g_scanS[idx] = s;
        s = fmaf(g_scanA[idx], s, g_scanB[idx]);
    }
}

__global__ __launch_bounds__(256) void scan_phase3(
    const float* __restrict__ dt, const float* __restrict__ z,
    const float* __restrict__ Bi, const float* __restrict__ Ci,
    const float* __restrict__ gate, const float* __restrict__ A_log,
    __nv_bfloat16* __restrict__ y)
{
    int gth = blockIdx.x*256 + threadIdx.x;
    int chan = gth & 127, chunk = gth >> 7;
    int b = chan >> 6, sc = chan & 63;
    float A[16];
    #pragma unroll
    for (int st = 0; st < 16; st++) A[st] = -__expf(A_log[sc*STv + st]);
    float state[16];
    {
        int base = (chan*CH + chunk)*16;
        #pragma unroll
        for (int st = 0; st < 16; st++) state[st] = g_scanS[base+st];
    }
    int t0 = chunk*TSTEP;
    const float* dtp = dt   + ((size_t)b*Tv + t0)*SCv + sc;
    const float* zp  = z    + ((size_t)b*Tv + t0)*SCv + sc;
    const float* gp  = gate + ((size_t)b*Tv + t0)*SCv + sc;
    const float* Bp  = Bi + ((size_t)b*Tv + t0)*STv;
    const float* Cp  = Ci + ((size_t)b*Tv + t0)*STv;
    __nv_bfloat16* yp = y + ((size_t)b*Tv + t0)*SCv + sc;
    for (int tt = 0; tt < TSTEP; tt++) {
        float dtc = dtp[(size_t)tt*SCv];
        float zc  = zp [(size_t)tt*SCv];
        float dz  = dtc*zc;
        float4 B0 = *(const float4*)&Bp[tt*STv + 0];
        float4 B1 = *(const float4*)&Bp[tt*STv + 4];
        float4 B2 = *(const float4*)&Bp[tt*STv + 8];
        float4 B3 = *(const float4*)&Bp[tt*STv + 12];
        float4 C0 = *(const float4*)&Cp[tt*STv + 0];
        float4 C1 = *(const float4*)&Cp[tt*STv + 4];
        float4 C2 = *(const float4*)&Cp[tt*STv + 8];
        float4 C3 = *(const float4*)&Cp[tt*STv + 12];
        float Bvv[16] = {B0.x,B0.y,B0.z,B0.w, B1.x,B1.y,B1.z,B1.w,
                         B2.x,B2.y,B2.z,B2.w, B3.x,B3.y,B3.z,B3.w};
        float Cvv[16] = {C0.x,C0.y,C0.z,C0.w, C1.x,C1.y,C1.z,C1.w,
                         C2.x,C2.y,C2.z,C2.w, C3.x,C3.y,C3.z,C3.w};
        float p0 = 0.f, p1 = 0.f, p2 = 0.f, p3 = 0.f;
        #pragma unroll
        for (int st = 0; st < 16; st += 4) {
            float ab;
            ab = fmaf(dtc, A[st+0], 1.f); state[st+0] = fmaf(ab, state[st+0], dz*Bvv[st+0]); p0 = fmaf(state[st+0], Cvv[st+0], p0);
            ab = fmaf(dtc, A[st+1], 1.f); state[st+1] = fmaf(ab, state[st+1], dz*Bvv[st+1]); p1 = fmaf(state[st+1], Cvv[st+1], p1);
            ab = fmaf(dtc, A[st+2], 1.f); state[st+2] = fmaf(ab, state[st+2], dz*Bvv[st+2]); p2 = fmaf(state[st+2], Cvv[st+2], p2);
            ab = fmaf(dtc, A[st+3], 1.f); state[st+3] = fmaf(ab, state[st+3], dz*Bvv[st+3]); p3 = fmaf(state[st+3], Cvv[st+3], p3);
        }
        float p = (p0 + p1) + (p2 + p3);
        yp[(size_t)tt*SCv] = __float2bfloat16(p * gp[(size_t)tt*SCv]);
    }
}

// ---------------- launch ----------------
extern "C" void kernel_launch(void* const* d_in, const int* in_sizes, int n_in,
                              void* d_out, int out_size)
{
    const float* x      = (const float*)d_in[0];
    const float* qkv_w  = (const float*)d_in[1];
    const float* o_w    = (const float*)d_in[2];
    const float* n1w    = (const float*)d_in[3];
    const float* n2w    = (const float*)d_in[4];
    const float* in_w   = (const float*)d_in[5];
    const float* out_w  = (const float*)d_in[6];
    const float* A_log  = (const float*)d_in[7];
    const float* Bp_w   = (const float*)d_in[8];
    const float* Cp_w   = (const float*)d_in[9];
    const float* dt_w   = (const float*)d_in[10];
    const float* dt_b   = (const float*)d_in[11];
    const float* gate_w = (const float*)d_in[12];
    float* out = (float*)d_out;

    __nv_bfloat16 *hb,*qkb,*vTb,*attnb,*h2b,*yb16,*wq,*wo,*wzg,*wout;
    float *x1,*zb,*gateb,*Bib,*Cib,*dtb,*zgacc;
    cudaGetSymbolAddress((void**)&hb,   g_h);
    cudaGetSymbolAddress((void**)&qkb,  g_qk);
    cudaGetSymbolAddress((void**)&vTb,  g_vT);
    cudaGetSymbolAddress((void**)&attnb,g_attn);
    cudaGetSymbolAddress((void**)&x1,   g_x1);
    cudaGetSymbolAddress((void**)&h2b,  g_h2);
    cudaGetSymbolAddress((void**)&zb,   g_z);
    cudaGetSymbolAddress((void**)&gateb,g_gate);
    cudaGetSymbolAddress((void**)&Bib,  g_Bi);
    cudaGetSymbolAddress((void**)&Cib,  g_Ci);
    cudaGetSymbolAddress((void**)&dtb,  g_dt);
    cudaGetSymbolAddress((void**)&yb16, g_y);
    cudaGetSymbolAddress((void**)&zgacc,g_zgacc);
    cudaGetSymbolAddress((void**)&wq,   g_wq);
    cudaGetSymbolAddress((void**)&wo,   g_wo);
    cudaGetSymbolAddress((void**)&wzg,  g_wzg);
    cudaGetSymbolAddress((void**)&wout, g_wout);

    const int gemm_smem = 6*GSTG*2;     // 61440 B
    const int attn_smem = 6*STAGEH*2;   // 110592 B
    cudaFuncSetAttribute(gemm_bf16, cudaFuncAttributeMaxDynamicSharedMemorySize, gemm_smem);
    cudaFuncSetAttribute(attn_mma_kernel, cudaFuncAttributeMaxDynamicSharedMemorySize, attn_smem);

    // 0. convert all weights to bf16 (single launch)
    conv_all<<<8576, 256>>>(qkv_w, o_w, in_w, gate_w, out_w);
    // 1. rmsnorm1 -> bf16
    rmsnorm_kernel<<<Mrows, 256>>>(x, n1w, hb);
    // 2. qkv: Q,K -> g_qk (bf16), V -> g_vT (transposed bf16)
    gemm_bf16<<<dim3(24, 32), 256, gemm_smem>>>(hb, wq, nullptr, qkb, vTb,
                                     Mrows, 3*Dv, 2*Dv, Dv, Dv, 2, 3, 2*Dv, 0);
    // 3. attention -> bf16
    attn_mma_kernel<<<dim3(Tv/128, Hv, Bv), 256, attn_smem>>>(qkb, vTb, attnb);
    // 4. x1 = x + attn @ o_w^T (fp32)
    gemm_bf16<<<dim3(8, 32), 256, gemm_smem>>>(attnb, wo, x, x1, nullptr,
                                    Mrows, Dv, Dv, Dv, Dv, 1, 1, Dv, 0);
    // 5. rmsnorm2 -> bf16
    rmsnorm_kernel<<<Mrows, 256>>>(x1, n2w, h2b);
    // 6. z/gate split-K (8 splits of K=128) -> partials
    gemm_bf16<<<dim3(1, 32, ZSPLIT), 256, gemm_smem>>>(h2b, wzg, nullptr, zgacc, nullptr,
                                    Mrows, 2*SCv, 2*SCv, Dv/ZSPLIT, Dv, 0, 0, 2*SCv, 0);
    // 7. fused reduce(z/gate) + Bi/Ci/dt
    gemm_bcd<<<64, 256>>>(Bp_w, Cp_w, dt_w, dt_b, zb, gateb, Bib, Cib, dtb);
    // 8. parallel scan -> y bf16
    scan_phase1<<<32, 256>>>(dtb, zb, Bib, A_log);
    scan_phase2<<<8, 256>>>();
    scan_phase3<<<32, 256>>>(dtb, zb, Bib, Cib, gateb, A_log, yb16);
    // 9. out = x1 + y @ out_w^T (fp32)
    gemm_bf16<<<dim3(8, 32), 256, gemm_smem>>>(yb16, wout, x1, out, nullptr,
                                    Mrows, Dv, Dv, SCv, SCv, 1, 1, Dv, 0);
}

// round 14
// speedup vs baseline: 1.0267x; 1.0267x over previous
#include <cuda_runtime.h>
#include <cuda_bf16.h>
#include <math.h>
#include <cstdint>

#define Bv 2
#define Tv 2048
#define Dv 1024
#define Hv 16
#define HDv 64
#define SCv 64
#define STv 16
#define Mrows (Bv*Tv)   // 4096
#define EPSR 1.1920929e-07f
#define CH 64
#define TSTEP (Tv/CH)   // 32
#define ZSPLIT 8

// ---------------- scratch (device globals) ----------------
__device__ __nv_bfloat16 g_h   [Mrows*Dv];
__device__ __nv_bfloat16 g_qk  [Mrows*2*Dv];
__device__ __nv_bfloat16 g_vT  [Dv*Mrows];
__device__ __nv_bfloat16 g_attn[Mrows*Dv];
__device__ float         g_x1  [Mrows*Dv];
__device__ __nv_bfloat16 g_h2  [Mrows*Dv];
__device__ float g_z   [Mrows*SCv];
__device__ float g_gate[Mrows*SCv];
__device__ float g_Bi  [Mrows*STv];
__device__ float g_Ci  [Mrows*STv];
__device__ float g_dt  [Mrows*SCv];
__device__ __nv_bfloat16 g_y [Mrows*SCv];
__device__ float g_scanA[128*CH*16];
__device__ float g_scanB[128*CH*16];
__device__ float g_scanS[128*CH*16];
__device__ float g_zgacc[ZSPLIT*Mrows*128];
__device__ __nv_bfloat16 g_wq  [3*Dv*Dv];
__device__ __nv_bfloat16 g_wo  [Dv*Dv];
__device__ __nv_bfloat16 g_wzg [2*SCv*Dv];
__device__ __nv_bfloat16 g_wout[Dv*SCv];

__device__ __forceinline__ uint32_t packbf(float a, float b) {
    __nv_bfloat162 t = __floats2bfloat162_rn(a, b);
    return *reinterpret_cast<uint32_t*>(&t);
}
__device__ __forceinline__ float ex2(float x) {
    float y;
    asm("ex2.approx.f32 %0, %1;" : "=f"(y) : "f"(x));
    return y;
}
__device__ __forceinline__ uint32_t ex2b2(uint32_t x) {
    uint32_t y;
    asm("ex2.approx.ftz.bf16x2 %0, %1;" : "=r"(y) : "r"(x));
    return y;
}
__device__ __forceinline__ float bf2sum(uint32_t w) {
    float lo = __uint_as_float(w << 16);
    float hi = __uint_as_float(w & 0xffff0000u);
    return lo + hi;
}
__device__ __forceinline__ uint32_t scale_pack(uint32_t w, float s) {
    __nv_bfloat162 t = *reinterpret_cast<__nv_bfloat162*>(&w);
    return packbf(__bfloat162float(t.x)*s, __bfloat162float(t.y)*s);
}

__device__ __forceinline__ void mma_bf16(float& d0, float& d1, float& d2, float& d3,
                                         uint32_t a0, uint32_t a1, uint32_t a2, uint32_t a3,
                                         uint32_t b0, uint32_t b1) {
    asm volatile(
        "mma.sync.aligned.m16n8k16.row.col.f32.bf16.bf16.f32 "
        "{%0,%1,%2,%3}, {%4,%5,%6,%7}, {%8,%9}, {%0,%1,%2,%3};"
        : "+f"(d0), "+f"(d1), "+f"(d2), "+f"(d3)
        : "r"(a0), "r"(a1), "r"(a2), "r"(a3), "r"(b0), "r"(b1));
}

__device__ __forceinline__ void ldsm4(uint32_t& r0, uint32_t& r1, uint32_t& r2, uint32_t& r3,
                                      uint32_t addr) {
    asm volatile("ldmatrix.sync.aligned.m8n8.x4.shared.b16 {%0,%1,%2,%3}, [%4];"
        : "=r"(r0), "=r"(r1), "=r"(r2), "=r"(r3) : "r"(addr));
}

__device__ __forceinline__ void cp16h(__nv_bfloat16* dst, const __nv_bfloat16* src) {
    uint32_t d = (uint32_t)__cvta_generic_to_shared(dst);
    asm volatile("cp.async.cg.shared.global [%0], [%1], 16;" :: "r"(d), "l"(src));
}
#define CP_COMMIT()  asm volatile("cp.async.commit_group;" ::)
#define CP_WAIT2()   asm volatile("cp.async.wait_group 2;" ::)
#define CP_WAIT1()   asm volatile("cp.async.wait_group 1;" ::)
#define CP_WAIT0()   asm volatile("cp.async.wait_group 0;" ::)

// ---------------- merged f32 -> bf16 convert of ALL weights ----------------
#define N2_Q   1572864
#define N2_O   524288
#define N2_S   32768
__global__ __launch_bounds__(256) void conv_all(
    const float* __restrict__ qkv_w, const float* __restrict__ o_w,
    const float* __restrict__ in_w, const float* __restrict__ gate_w,
    const float* __restrict__ out_w)
{
    int i = blockIdx.x*256 + threadIdx.x;
    const float* src; __nv_bfloat162* dst; int j;
    if (i < N2_Q)                        { src = qkv_w;  dst = (__nv_bfloat162*)g_wq;   j = i; }
    else if ((j = i - N2_Q) < N2_O)      { src = o_w;    dst = (__nv_bfloat162*)g_wo; }
    else if ((j = j - N2_O) < N2_S)      { src = in_w;   dst = (__nv_bfloat162*)g_wzg; }
    else if ((j = j - N2_S) < N2_S)      { src = gate_w; dst = (__nv_bfloat162*)g_wzg + N2_S; }
    else if ((j = j - N2_S) < N2_S)      { src = out_w;  dst = (__nv_bfloat162*)g_wout; }
    else return;
    float2 v = ((const float2*)src)[j];
    dst[j] = __floats2bfloat162_rn(v.x, v.y);
}

// ---------------- RMSNorm -> bf16 ----------------
__global__ __launch_bounds__(256) void rmsnorm_kernel(
    const float* __restrict__ x, const float* __restrict__ w, __nv_bfloat16* __restrict__ o)
{
    int row = blockIdx.x;
    const float4* xr = (const float4*)(x + (size_t)row*Dv);
    float4 v = xr[threadIdx.x];
    float ss = v.x*v.x + v.y*v.y + v.z*v.z + v.w*v.w;
    #pragma unroll
    for (int off=16; off; off>>=1) ss += __shfl_xor_sync(0xffffffffu, ss, off);
    __shared__ float sm[8];
    int wid = threadIdx.x>>5, lane = threadIdx.x&31;
    if (lane==0) sm[wid] = ss;
    __syncthreads();
    float tot = sm[0]+sm[1]+sm[2]+sm[3]+sm[4]+sm[5]+sm[6]+sm[7];
    float scale = rsqrtf(tot*(1.0f/Dv) + EPSR);
    const float4* wr = (const float4*)w;
    float4 wv = wr[threadIdx.x];
    uint2 st = make_uint2(packbf(v.x*scale*wv.x, v.y*scale*wv.y),
                          packbf(v.z*scale*wv.z, v.w*scale*wv.w));
    *(uint2*)&o[(size_t)row*Dv + threadIdx.x*4] = st;
}

// ---------------- bf16 GEMM: 3-stage cp.async, split-K capable --------------
// modes: 0 fp32 (with split-K offset); 1 fp32+res; 2 bf16; 3 bf16 transposed; 4 fp32 silu
#define GLDH 40
#define GSTG (128*GLDH)
__global__ __launch_bounds__(256, 2) void gemm_bf16(
    const __nv_bfloat16* __restrict__ A, const __nv_bfloat16* __restrict__ W,
    const float* __restrict__ res, void* __restrict__ Cp, void* __restrict__ C2p,
    int M, int N, int nsplit, int K, int Kstride, int mode1, int mode2, int ld1, int ld2)
{
    extern __shared__ __nv_bfloat16 smg[];
    __nv_bfloat16* Asm = smg;
    __nv_bfloat16* Wsm = smg + 3*GSTG;

    const int tid = threadIdx.x;
    const int w   = tid >> 5;
    const int l   = tid & 31;
    const int g   = l >> 2;
    const int q   = l & 3;
    const int wm  = w >> 1;
    const int wn  = w & 1;
    const int bm  = blockIdx.y * 128;
    const int bn  = blockIdx.x * 128;

    const __nv_bfloat16* Ab = A + (size_t)blockIdx.z * K;
    const __nv_bfloat16* Wb = W + (size_t)blockIdx.z * K;

    const int lr = l & 7, lt = l >> 3;
    const uint32_t sAb = (uint32_t)__cvta_generic_to_shared(Asm);
    const uint32_t sWb = (uint32_t)__cvta_generic_to_shared(Wsm);
    const uint32_t aOff = (uint32_t)((((lt & 1)*8 + lr)*GLDH + (lt >> 1)*8) * 2);
    const uint32_t bOff = (uint32_t)((((lt >> 1)*8 + lr)*GLDH + (lt & 1)*8) * 2);

    const int crow = tid >> 2, cseg = (tid & 3) * 8;

    float c[2][8][4];
    #pragma unroll
    for (int i=0;i<2;i++)
        #pragma unroll
        for (int nj=0;nj<8;nj++)
            #pragma unroll
            for (int e=0;e<4;e++) c[i][nj][e] = 0.f;

    const int nch = K >> 5;

    #pragma unroll
    for (int p = 0; p < 2; p++) {
        #pragma unroll
        for (int ii = 0; ii < 2; ii++) {
            int row = crow + ii*64;
            cp16h(Asm + p*GSTG + row*GLDH + cseg, Ab + (size_t)(bm + row)*Kstride + p*32 + cseg);
            cp16h(Wsm + p*GSTG + row*GLDH + cseg, Wb + (size_t)(bn + row)*Kstride + p*32 + cseg);
        }
        CP_COMMIT();
    }

    for (int i = 0; i < nch; i++) {
        if (i == nch - 1) { CP_WAIT0(); } else { CP_WAIT1(); }
        __syncthreads();
        if (i + 2 < nch) {
            int st = (i + 2) % 3, kn = (i + 2) * 32;
            #pragma unroll
            for (int ii = 0; ii < 2; ii++) {
                int row = crow + ii*64;
                cp16h(Asm + st*GSTG + row*GLDH + cseg, Ab + (size_t)(bm + row)*Kstride + kn + cseg);
                cp16h(Wsm + st*GSTG + row*GLDH + cseg, Wb + (size_t)(bn + row)*Kstride + kn + cseg);
            }
            CP_COMMIT();
        }

        const uint32_t sa = sAb + (uint32_t)((i % 3) * GSTG * 2);
        const uint32_t sw = sWb + (uint32_t)((i % 3) * GSTG * 2);
        #pragma unroll
        for (int kc2 = 0; kc2 < 2; kc2++) {
            uint32_t a[2][4];
            #pragma unroll
            for (int ii = 0; ii < 2; ii++)
                ldsm4(a[ii][0], a[ii][1], a[ii][2], a[ii][3],
                      sa + aOff + (uint32_t)(((wm*32 + ii*16)*GLDH + kc2*16) * 2));
            uint32_t bfr[8][2];
            #pragma unroll
            for (int ncp = 0; ncp < 4; ncp++) {
                uint32_t x0, x1, x2, x3;
                ldsm4(x0, x1, x2, x3,
                      sw + bOff + (uint32_t)(((wn*64 + ncp*16)*GLDH + kc2*16) * 2));
                bfr[2*ncp][0] = x0; bfr[2*ncp][1] = x1;
                bfr[2*ncp+1][0] = x2; bfr[2*ncp+1][1] = x3;
            }
            #pragma unroll
            for (int ii = 0; ii < 2; ii++)
                #pragma unroll
                for (int nj = 0; nj < 8; nj++)
                    mma_bf16(c[ii][nj][0], c[ii][nj][1], c[ii][nj][2], c[ii][nj][3],
                             a[ii][0], a[ii][1], a[ii][2], a[ii][3], bfr[nj][0], bfr[nj][1]);
        }
    }

    #pragma unroll
    for (int i = 0; i < 2; i++) {
        #pragma unroll
        for (int nj = 0; nj < 8; nj++) {
            int row0 = bm + wm*32 + i*16 + g;
            int row1 = row0 + 8;
            int col  = bn + wn*64 + nj*8 + 2*q;
            bool first = (col < nsplit);
            int mode = first ? mode1 : mode2;
            float v0 = c[i][nj][0], v1 = c[i][nj][1], v2 = c[i][nj][2], v3 = c[i][nj][3];
            if (mode == 1) {
                v0 += res[(size_t)row0*N + col];
                v1 += res[(size_t)row0*N + col + 1];
                v2 += res[(size_t)row1*N + col];
                v3 += res[(size_t)row1*N + col + 1];
            } else if (mode == 4) {
                v0 = v0 / (1.f + __expf(-v0));
                v1 = v1 / (1.f + __expf(-v1));
                v2 = v2 / (1.f + __expf(-v2));
                v3 = v3 / (1.f + __expf(-v3));
            }
            if (mode == 2) {
                __nv_bfloat16* O = (__nv_bfloat16*)(first ? Cp : C2p);
                int ld = first ? ld1 : ld2;
                int cc = first ? col : col - nsplit;
                *(uint32_t*)&O[(size_t)row0*ld + cc] = packbf(v0, v1);
                *(uint32_t*)&O[(size_t)row1*ld + cc] = packbf(v2, v3);
            } else if (mode == 3) {
                __nv_bfloat16* O = (__nv_bfloat16*)C2p;
                int cc = col - nsplit;
                O[(size_t)cc*M + row0]     = __float2bfloat16(v0);
                O[(size_t)(cc+1)*M + row0] = __float2bfloat16(v1);
                O[(size_t)cc*M + row1]     = __float2bfloat16(v2);
                O[(size_t)(cc+1)*M + row1] = __float2bfloat16(v3);
            } else {
                float* O = (float*)(first ? Cp : C2p);
                int ld = first ? ld1 : ld2;
                int cc = first ? col : col - nsplit;
                if (mode == 0) O += (size_t)blockIdx.z * M * ld;
                *(float2*)&O[(size_t)row0*ld + cc] = make_float2(v0, v1);
                *(float2*)&O[(size_t)row1*ld + cc] = make_float2(v2, v3);
            }
        }
    }
}

// ---------------- z/gate split-K reduce + silu ----------------
__global__ __launch_bounds__(256) void zg_reduce(
    float* __restrict__ z, float* __restrict__ gate)
{
    int idx = blockIdx.x*256 + threadIdx.x;   // 0..Mrows*128-1
    float s = 0.f;
    #pragma unroll
    for (int p = 0; p < ZSPLIT; p++) s += g_zgacc[(size_t)p*Mrows*128 + idx];
    int row = idx >> 7, col = idx & 127;
    if (col < SCv) z[(size_t)row*SCv + col] = s;
    else gate[(size_t)row*SCv + col - SCv] = s / (1.f + __expf(-s));
}

// ---------------- fused Bi/Ci/dt (fp32) ----------------
__global__ __launch_bounds__(256) void gemm_bcd(
    const float* __restrict__ z, const float* __restrict__ Bp_w,
    const float* __restrict__ Cp_w, const float* __restrict__ dt_w,
    const float* __restrict__ dt_b,
    float* __restrict__ Bi, float* __restrict__ Ci, float* __restrict__ dt)
{
    __shared__ float Zs[64*68];
    __shared__ float Wt[64*100];
    const int tid = threadIdx.x;
    const int bm = blockIdx.x*64;

    for (int t = tid; t < 1024; t += 256) {
        int row = t >> 4, k4 = (t & 15) << 2;
        float4 v = *(const float4*)&z[(size_t)(bm + row)*SCv + k4];
        Zs[row*68 + k4 + 0] = v.x; Zs[row*68 + k4 + 1] = v.y;
        Zs[row*68 + k4 + 2] = v.z; Zs[row*68 + k4 + 3] = v.w;
    }
    for (int idx = tid; idx < 96*64; idx += 256) {
        int r = idx >> 6, c = idx & 63;
        float v = (r < 16) ? Bp_w[r*SCv + c] : (r < 32) ? Cp_w[(r-16)*SCv + c] : dt_w[(r-32)*SCv + c];
        Wt[c*100 + r] = v;
    }
    __syncthreads();

    const int ty = tid >> 4, tx = tid & 15;
    float acc[4][6];
    #pragma unroll
    for (int i=0;i<4;i++)
        #pragma unroll
        for (int j=0;j<6;j++) acc[i][j] = 0.f;

    #pragma unroll 4
    for (int k = 0; k < 64; k++) {
        float a[4], bb[6];
        #pragma unroll
        for (int i=0;i<4;i++) a[i] = Zs[(ty*4+i)*68 + k];
        #pragma unroll
        for (int j=0;j<6;j++) bb[j] = Wt[k*100 + tx*6 + j];
        #pragma unroll
        for (int i=0;i<4;i++)
            #pragma unroll
            for (int j=0;j<6;j++) acc[i][j] = fmaf(a[i], bb[j], acc[i][j]);
    }

    #pragma unroll
    for (int i=0;i<4;i++) {
        int row = bm + ty*4 + i;
        #pragma unroll
        for (int j=0;j<6;j++) {
            int c = tx*6 + j;
            float v = acc[i][j];
            if (c < 16) {
                Bi[(size_t)row*STv + c] = v;
            } else if (c < 32) {
                Ci[(size_t)row*STv + (c-16)] = v;
            } else {
                v += dt_b[c-32];
                dt[(size_t)row*SCv + (c-32)] = (v > 20.f) ? v : log1pf(__expf(v));
            }
        }
    }
}

// ---------------- Flash attention v8: 6-stage, sync every 2 tiles ----------
#define KS_LDH 72
#define STAGEH (64*KS_LDH*2)
__global__ __launch_bounds__(256, 2) void attn_mma_kernel(
    const __nv_bfloat16* __restrict__ qk, const __nv_bfloat16* __restrict__ vT,
    __nv_bfloat16* __restrict__ out)
{
    extern __shared__ __nv_bfloat16 smh[];

    const int tid = threadIdx.x;
    const int w   = tid >> 5;
    const int l   = tid & 31;
    const int g   = l >> 2;
    const int q   = l & 3;
    const int qb  = (int)gridDim.x - 1 - (int)blockIdx.x;
    const int h = blockIdx.y, b = blockIdx.z;
    const int qrow0 = qb*128 + w*16;

    const int lr = l & 7, lt = l >> 3;
    const uint32_t smbase = (uint32_t)__cvta_generic_to_shared(smh);
    const uint32_t bOff = (uint32_t)((((lt >> 1)*8 + lr)*KS_LDH + (lt & 1)*8) * 2);

    const float QSC = 0.125f * 1.4426950408889634f;
    uint32_t qa[4][4];
    {
        const uint32_t* Qw0 = (const uint32_t*)(qk + ((size_t)(b*Tv + qrow0 + g    ))*(2*Dv) + h*HDv);
        const uint32_t* Qw1 = (const uint32_t*)(qk + ((size_t)(b*Tv + qrow0 + g + 8))*(2*Dv) + h*HDv);
        #pragma unroll
        for (int kc = 0; kc < 4; kc++) {
            qa[kc][0] = scale_pack(Qw0[kc*8 + q    ], QSC);
            qa[kc][1] = scale_pack(Qw1[kc*8 + q    ], QSC);
            qa[kc][2] = scale_pack(Qw0[kc*8 + q + 4], QSC);
            qa[kc][3] = scale_pack(Qw1[kc*8 + q + 4], QSC);
        }
    }

    float o[8][4];
    #pragma unroll
    for (int nc = 0; nc < 8; nc++)
        #pragma unroll
        for (int e = 0; e < 4; e++) o[nc][e] = 0.f;
    float mA = -1e30f, mB = -1e30f, lA = 0.f, lB = 0.f;

    const int ntiles = 2*qb + 2;   // always even, >= 2

    #pragma unroll
    for (int p = 0; p < 4; p++) {
        if (p < ntiles) {
            __nv_bfloat16* Kb = smh + p*STAGEH;
            __nv_bfloat16* Vb = Kb + 64*KS_LDH;
            #pragma unroll
            for (int i = 0; i < 2; i++) {
                int idx = tid + i*256;
                int r = idx >> 3, seg = (idx & 7) * 8;
                cp16h(Kb + r*KS_LDH + seg, qk + ((size_t)(b*Tv + p*64 + r))*(2*Dv) + Dv + h*HDv + seg);
                cp16h(Vb + r*KS_LDH + seg, vT + ((size_t)(h*HDv + r))*Mrows + b*Tv + p*64 + seg);
            }
        }
        CP_COMMIT();
    }

    for (int kt = 0; kt < ntiles; kt += 2) {
        CP_WAIT2();
        __syncthreads();
        #pragma unroll
        for (int pp = 0; pp < 2; pp++) {
            int t = kt + 4 + pp;
            if (t < ntiles) {
                int st = t % 6;
                __nv_bfloat16* Kb = smh + st*STAGEH;
                __nv_bfloat16* Vb = Kb + 64*KS_LDH;
                #pragma unroll
                for (int i = 0; i < 2; i++) {
                    int idx = tid + i*256;
                    int r = idx >> 3, seg = (idx & 7) * 8;
                    cp16h(Kb + r*KS_LDH + seg, qk + ((size_t)(b*Tv + t*64 + r))*(2*Dv) + Dv + h*HDv + seg);
                    cp16h(Vb + r*KS_LDH + seg, vT + ((size_t)(h*HDv + r))*Mrows + b*Tv + t*64 + seg);
                }
            }
            CP_COMMIT();
        }

        #pragma unroll
        for (int sub = 0; sub < 2; sub++) {
            const int kti = kt + sub;
            const int kbase = kti*64;
            const uint32_t kst = smbase + (uint32_t)(((kti % 6)*STAGEH) * 2);
            const uint32_t vst = kst + (uint32_t)(64*KS_LDH*2);

            float s[8][4];
            #pragma unroll
            for (int nc = 0; nc < 8; nc++) {
                s[nc][0] = 0.f; s[nc][1] = 0.f; s[nc][2] = 0.f; s[nc][3] = 0.f;
            }
            #pragma unroll
            for (int ncp = 0; ncp < 4; ncp++) {
                #pragma unroll
                for (int kc = 0; kc < 4; kc++) {
                    uint32_t b0, b1, b2, b3;
                    ldsm4(b0, b1, b2, b3, kst + bOff + (uint32_t)(((ncp*16)*KS_LDH + kc*16) * 2));
                    mma_bf16(s[2*ncp][0], s[2*ncp][1], s[2*ncp][2], s[2*ncp][3],
                             qa[kc][0], qa[kc][1], qa[kc][2], qa[kc][3], b0, b1);
                    mma_bf16(s[2*ncp+1][0], s[2*ncp+1][1], s[2*ncp+1][2], s[2*ncp+1][3],
                             qa[kc][0], qa[kc][1], qa[kc][2], qa[kc][3], b2, b3);
                }
            }

            if (kbase + 63 > qrow0) {
                int rowA = qrow0 + g, rowB = qrow0 + g + 8;
                #pragma unroll
                for (int nc = 0; nc < 8; nc++) {
                    int c0 = kbase + nc*8 + 2*q, c1 = c0 + 1;
                    if (c0 > rowA) s[nc][0] = -1e30f;
                    if (c1 > rowA) s[nc][1] = -1e30f;
                    if (c0 > rowB) s[nc][2] = -1e30f;
                    if (c1 > rowB) s[nc][3] = -1e30f;
                }
            }

            float rmA = -1e30f, rmB = -1e30f;
            #pragma unroll
            for (int nc = 0; nc < 8; nc++) {
                rmA = fmaxf(rmA, fmaxf(s[nc][0], s[nc][1]));
                rmB = fmaxf(rmB, fmaxf(s[nc][2], s[nc][3]));
            }
            rmA = fmaxf(rmA, __shfl_xor_sync(0xffffffffu, rmA, 1));
            rmA = fmaxf(rmA, __shfl_xor_sync(0xffffffffu, rmA, 2));
            rmB = fmaxf(rmB, __shfl_xor_sync(0xffffffffu, rmB, 1));
            rmB = fmaxf(rmB, __shfl_xor_sync(0xffffffffu, rmB, 2));
            float mnA = fmaxf(mA, rmA), mnB = fmaxf(mB, rmB);
            float corrA = ex2(mA - mnA), corrB = ex2(mB - mnB);
            mA = mnA; mB = mnB;

            uint32_t pa[4][4];
            #pragma unroll
            for (int kc = 0; kc < 4; kc++) {
                pa[kc][0] = ex2b2(packbf(s[2*kc][0]   - mnA, s[2*kc][1]   - mnA));
                pa[kc][1] = ex2b2(packbf(s[2*kc][2]   - mnB, s[2*kc][3]   - mnB));
                pa[kc][2] = ex2b2(packbf(s[2*kc+1][0] - mnA, s[2*kc+1][1] - mnA));
                pa[kc][3] = ex2b2(packbf(s[2*kc+1][2] - mnB, s[2*kc+1][3] - mnB));
            }

            #pragma unroll
            for (int nc = 0; nc < 8; nc++) {
                o[nc][0] *= corrA; o[nc][1] *= corrA;
                o[nc][2] *= corrB; o[nc][3] *= corrB;
            }
            #pragma unroll
            for (int ncp = 0; ncp < 4; ncp++) {
                #pragma unroll
                for (int kc = 0; kc < 4; kc++) {
                    uint32_t v0, v1, v2, v3;
                    ldsm4(v0, v1, v2, v3, vst + bOff + (uint32_t)(((ncp*16)*KS_LDH + kc*16) * 2));
                    mma_bf16(o[2*ncp][0], o[2*ncp][1], o[2*ncp][2], o[2*ncp][3],
                             pa[kc][0], pa[kc][1], pa[kc][2], pa[kc][3], v0, v1);
                    mma_bf16(o[2*ncp+1][0], o[2*ncp+1][1], o[2*ncp+1][2], o[2*ncp+1][3],
                             pa[kc][0], pa[kc][1], pa[kc][2], pa[kc][3], v2, v3);
                }
            }

            float rsA = 0.f, rsB = 0.f;
            #pragma unroll
            for (int kc = 0; kc < 4; kc++) {
                rsA += bf2sum(pa[kc][0]) + bf2sum(pa[kc][2]);
                rsB += bf2sum(pa[kc][1]) + bf2sum(pa[kc][3]);
            }
            rsA += __shfl_xor_sync(0xffffffffu, rsA, 1);
            rsA += __shfl_xor_sync(0xffffffffu, rsA, 2);
            rsB += __shfl_xor_sync(0xffffffffu, rsB, 1);
            rsB += __shfl_xor_sync(0xffffffffu, rsB, 2);
            lA = lA*corrA + rsA;
            lB = lB*corrB + rsB;
        }
    }

    float invA = 1.f / lA, invB = 1.f / lB;
    __nv_bfloat16* ob0 = out + ((size_t)(b*Tv + qrow0 + g    ))*Dv + h*HDv;
    __nv_bfloat16* ob1 = out + ((size_t)(b*Tv + qrow0 + g + 8))*Dv + h*HDv;
    #pragma unroll
    for (int nc = 0; nc < 8; nc++) {
        int c = nc*8 + 2*q;
        *(uint32_t*)&ob0[c] = packbf(o[nc][0]*invA, o[nc][1]*invA);
        *(uint32_t*)&ob1[c] = packbf(o[nc][2]*invB, o[nc][3]*invB);
    }
}

// ---------------- Parallel selective scan (CH=64) ----------------
__global__ __launch_bounds__(256) void scan_phase1(
    const float* __restrict__ dt, const float* __restrict__ z,
    const float* __restrict__ Bi, const float* __restrict__ A_log)
{
    int gth = blockIdx.x*256 + threadIdx.x;
    int chan = gth & 127, chunk = gth >> 7;
    int b = chan >> 6, sc = chan & 63;
    float A[16];
    #pragma unroll
    for (int st = 0; st < 16; st++) A[st] = -__expf(A_log[sc*STv + st]);
    float aP[16], bP[16];
    #pragma unroll
    for (int st = 0; st < 16; st++) { aP[st] = 1.f; bP[st] = 0.f; }
    int t0 = chunk*TSTEP;
    const float* dtp = dt + ((size_t)b*Tv + t0)*SCv + sc;
    const float* zp  = z  + ((size_t)b*Tv + t0)*SCv + sc;
    const float* Bp  = Bi + ((size_t)b*Tv + t0)*STv;
    for (int tt = 0; tt < TSTEP; tt++) {
        float dtc = dtp[(size_t)tt*SCv];
        float zc  = zp [(size_t)tt*SCv];
        float dz  = dtc*zc;
        float4 B0 = *(const float4*)&Bp[tt*STv + 0];
        float4 B1 = *(const float4*)&Bp[tt*STv + 4];
        float4 B2 = *(const float4*)&Bp[tt*STv + 8];
        float4 B3 = *(const float4*)&Bp[tt*STv + 12];
        float Bvv[16] = {B0.x,B0.y,B0.z,B0.w, B1.x,B1.y,B1.z,B1.w,
                         B2.x,B2.y,B2.z,B2.w, B3.x,B3.y,B3.z,B3.w};
        #pragma unroll
        for (int st = 0; st < 16; st++) {
            float ab = fmaf(dtc, A[st], 1.f);
            aP[st] *= ab;
            bP[st] = fmaf(ab, bP[st], dz*Bvv[st]);
        }
    }
    int base = (chan*CH + chunk)*16;
    #pragma unroll
    for (int st = 0; st < 16; st++) { g_scanA[base+st] = aP[st]; g_scanB[base+st] = bP[st]; }
}

__global__ __launch_bounds__(256) void scan_phase2()
{
    int gth = blockIdx.x*256 + threadIdx.x;
    int chan = gth >> 4, st = gth & 15;
    float s = 0.f;
    #pragma unroll 8
    for (int ch = 0; ch < CH; ch++) {
        int idx = (chan*CH + ch)*16 + st;
        g_scanS[idx] = s;
        s = fmaf(g_scanA[idx], s, g_scanB[idx]);
    }
}

__global__ __launch_bounds__(256) void scan_phase3(
    const float* __restrict__ dt, const float* __restrict__ z,
    const float* __restrict__ Bi, const float* __restrict__ Ci,
    const float* __restrict__ gate, const float* __restrict__ A_log,
    __nv_bfloat16* __restrict__ y)
{
    int gth = blockIdx.x*256 + threadIdx.x;
    int chan = gth & 127, chunk = gth >> 7;
    int b = chan >> 6, sc = chan & 63;
    float A[16];
    #pragma unroll
    for (int st = 0; st < 16; st++) A[st] = -__expf(A_log[sc*STv + st]);
    float state[16];
    {
        int base = (chan*CH + chunk)*16;
        #pragma unroll
        for (int st = 0; st < 16; st++) state[st] = g_scanS[base+st];
    }
    int t0 = chunk*TSTEP;
    const float* dtp = dt   + ((size_t)b*Tv + t0)*SCv + sc;
    const float* zp  = z    + ((size_t)b*Tv + t0)*SCv + sc;
    const float* gp  = gate + ((size_t)b*Tv + t0)*SCv + sc;
    const float* Bp  = Bi + ((size_t)b*Tv + t0)*STv;
    const float* Cp  = Ci + ((size_t)b*Tv + t0)*STv;
    __nv_bfloat16* yp = y + ((size_t)b*Tv + t0)*SCv + sc;
    for (int tt = 0; tt < TSTEP; tt++) {
        float dtc = dtp[(size_t)tt*SCv];
        float zc  = zp [(size_t)tt*SCv];
        float dz  = dtc*zc;
        float4 B0 = *(const float4*)&Bp[tt*STv + 0];
        float4 B1 = *(const float4*)&Bp[tt*STv + 4];
        float4 B2 = *(const float4*)&Bp[tt*STv + 8];
        float4 B3 = *(const float4*)&Bp[tt*STv + 12];
        float4 C0 = *(const float4*)&Cp[tt*STv + 0];
        float4 C1 = *(const float4*)&Cp[tt*STv + 4];
        float4 C2 = *(const float4*)&Cp[tt*STv + 8];
        float4 C3 = *(const float4*)&Cp[tt*STv + 12];
        float Bvv[16] = {B0.x,B0.y,B0.z,B0.w, B1.x,B1.y,B1.z,B1.w,
                         B2.x,B2.y,B2.z,B2.w, B3.x,B3.y,B3.z,B3.w};
        float Cvv[16] = {C0.x,C0.y,C0.z,C0.w, C1.x,C1.y,C1.z,C1.w,
                         C2.x,C2.y,C2.z,C2.w, C3.x,C3.y,C3.z,C3.w};
        float p0 = 0.f, p1 = 0.f, p2 = 0.f, p3 = 0.f;
        #pragma unroll
        for (int st = 0; st < 16; st += 4) {
            float ab;
            ab = fmaf(dtc, A[st+0], 1.f); state[st+0] = fmaf(ab, state[st+0], dz*Bvv[st+0]); p0 = fmaf(state[st+0], Cvv[st+0], p0);
            ab = fmaf(dtc, A[st+1], 1.f); state[st+1] = fmaf(ab, state[st+1], dz*Bvv[st+1]); p1 = fmaf(state[st+1], Cvv[st+1], p1);
            ab = fmaf(dtc, A[st+2], 1.f); state[st+2] = fmaf(ab, state[st+2], dz*Bvv[st+2]); p2 = fmaf(state[st+2], Cvv[st+2], p2);
            ab = fmaf(dtc, A[st+3], 1.f); state[st+3] = fmaf(ab, state[st+3], dz*Bvv[st+3]); p3 = fmaf(state[st+3], Cvv[st+3], p3);
        }
        float p = (p0 + p1) + (p2 + p3);
        yp[(size_t)tt*SCv] = __float2bfloat16(p * gp[(size_t)tt*SCv]);
    }
}

// ---------------- launch ----------------
extern "C" void kernel_launch(void* const* d_in, const int* in_sizes, int n_in,
                              void* d_out, int out_size)
{
    const float* x      = (const float*)d_in[0];
    const float* qkv_w  = (const float*)d_in[1];
    const float* o_w    = (const float*)d_in[2];
    const float* n1w    = (const float*)d_in[3];
    const float* n2w    = (const float*)d_in[4];
    const float* in_w   = (const float*)d_in[5];
    const float* out_w  = (const float*)d_in[6];
    const float* A_log  = (const float*)d_in[7];
    const float* Bp_w   = (const float*)d_in[8];
    const float* Cp_w   = (const float*)d_in[9];
    const float* dt_w   = (const float*)d_in[10];
    const float* dt_b   = (const float*)d_in[11];
    const float* gate_w = (const float*)d_in[12];
    float* out = (float*)d_out;

    __nv_bfloat16 *hb,*qkb,*vTb,*attnb,*h2b,*yb16,*wq,*wo,*wzg,*wout;
    float *x1,*zb,*gateb,*Bib,*Cib,*dtb,*zgacc;
    cudaGetSymbolAddress((void**)&hb,   g_h);
    cudaGetSymbolAddress((void**)&qkb,  g_qk);
    cudaGetSymbolAddress((void**)&vTb,  g_vT);
    cudaGetSymbolAddress((void**)&attnb,g_attn);
    cudaGetSymbolAddress((void**)&x1,   g_x1);
    cudaGetSymbolAddress((void**)&h2b,  g_h2);
    cudaGetSymbolAddress((void**)&zb,   g_z);
    cudaGetSymbolAddress((void**)&gateb,g_gate);
    cudaGetSymbolAddress((void**)&Bib,  g_Bi);
    cudaGetSymbolAddress((void**)&Cib,  g_Ci);
    cudaGetSymbolAddress((void**)&dtb,  g_dt);
    cudaGetSymbolAddress((void**)&yb16, g_y);
    cudaGetSymbolAddress((void**)&zgacc,g_zgacc);
    cudaGetSymbolAddress((void**)&wq,   g_wq);
    cudaGetSymbolAddress((void**)&wo,   g_wo);
    cudaGetSymbolAddress((void**)&wzg,  g_wzg);
    cudaGetSymbolAddress((void**)&wout, g_wout);

    const int gemm_smem = 6*GSTG*2;     // 61440 B
    const int attn_smem = 6*STAGEH*2;   // 110592 B
    cudaFuncSetAttribute(gemm_bf16, cudaFuncAttributeMaxDynamicSharedMemorySize, gemm_smem);
    cudaFuncSetAttribute(attn_mma_kernel, cudaFuncAttributeMaxDynamicSharedMemorySize, attn_smem);

    // 0. convert all weights to bf16 (single launch)
    conv_all<<<8576, 256>>>(qkv_w, o_w, in_w, gate_w, out_w);
    // 1. rmsnorm1 -> bf16
    rmsnorm_kernel<<<Mrows, 256>>>(x, n1w, hb);
    // 2. qkv: Q,K -> g_qk (bf16), V -> g_vT (transposed bf16)
    gemm_bf16<<<dim3(24, 32), 256, gemm_smem>>>(hb, wq, nullptr, qkb, vTb,
                                     Mrows, 3*Dv, 2*Dv, Dv, Dv, 2, 3, 2*Dv, 0);
    // 3. attention -> bf16
    attn_mma_kernel<<<dim3(Tv/128, Hv, Bv), 256, attn_smem>>>(qkb, vTb, attnb);
    // 4. x1 = x + attn @ o_w^T (fp32)
    gemm_bf16<<<dim3(8, 32), 256, gemm_smem>>>(attnb, wo, x, x1, nullptr,
                                    Mrows, Dv, Dv, Dv, Dv, 1, 1, Dv, 0);
    // 5. rmsnorm2 -> bf16
    rmsnorm_kernel<<<Mrows, 256>>>(x1, n2w, h2b);
    // 6. z/gate split-K (8 splits of K=128) -> partials, then parallel reduce
    gemm_bf16<<<dim3(1, 32, ZSPLIT), 256, gemm_smem>>>(h2b, wzg, nullptr, zgacc, nullptr,
                                    Mrows, 2*SCv, 2*SCv, Dv/ZSPLIT, Dv, 0, 0, 2*SCv, 0);
    zg_reduce<<<Mrows*128/256, 256>>>(zb, gateb);
    // 7. fused Bi/Ci/dt
    gemm_bcd<<<64, 256>>>(zb, Bp_w, Cp_w, dt_w, dt_b, Bib, Cib, dtb);
    // 8. parallel scan -> y bf16
    scan_phase1<<<32, 256>>>(dtb, zb, Bib, A_log);
    scan_phase2<<<8, 256>>>();
    scan_phase3<<<32, 256>>>(dtb, zb, Bib, Cib, gateb, A_log, yb16);
    // 9. out = x1 + y @ out_w^T (fp32)
    gemm_bf16<<<dim3(8, 32), 256, gemm_smem>>>(yb16, wout, x1, out, nullptr,
                                    Mrows, Dv, Dv, SCv, SCv, 1, 1, Dv, 0);
}

// round 15
// speedup vs baseline: 1.0724x; 1.0445x over previous
#include <cuda_runtime.h>
#include <cuda_bf16.h>
#include <math.h>
#include <cstdint>

#define Bv 2
#define Tv 2048
#define Dv 1024
#define Hv 16
#define HDv 64
#define SCv 64
#define STv 16
#define Mrows (Bv*Tv)   // 4096
#define EPSR 1.1920929e-07f
#define CH 64
#define TSTEP (Tv/CH)   // 32
#define ZSPLIT 4

// ---------------- scratch (device globals) ----------------
__device__ __nv_bfloat16 g_h   [Mrows*Dv];
__device__ __nv_bfloat16 g_qk  [Mrows*2*Dv];
__device__ __nv_bfloat16 g_vT  [Dv*Mrows];
__device__ __nv_bfloat16 g_attn[Mrows*Dv];
__device__ float         g_x1  [Mrows*Dv];
__device__ __nv_bfloat16 g_h2  [Mrows*Dv];
__device__ float g_z   [Mrows*SCv];
__device__ float g_gate[Mrows*SCv];
__device__ float g_Bi  [Mrows*STv];
__device__ float g_Ci  [Mrows*STv];
__device__ float g_dt  [Mrows*SCv];
__device__ __nv_bfloat16 g_y [Mrows*SCv];
__device__ float g_scanA[128*CH*16];
__device__ float g_scanB[128*CH*16];
__device__ float g_scanS[128*CH*16];
__device__ float g_zgacc[ZSPLIT*Mrows*128];
__device__ __nv_bfloat16 g_wq  [3*Dv*Dv];
__device__ __nv_bfloat16 g_wo  [Dv*Dv];
__device__ __nv_bfloat16 g_wzg [2*SCv*Dv];
__device__ __nv_bfloat16 g_wout[Dv*SCv];

__device__ __forceinline__ uint32_t packbf(float a, float b) {
    __nv_bfloat162 t = __floats2bfloat162_rn(a, b);
    return *reinterpret_cast<uint32_t*>(&t);
}
__device__ __forceinline__ float ex2(float x) {
    float y;
    asm("ex2.approx.f32 %0, %1;" : "=f"(y) : "f"(x));
    return y;
}
__device__ __forceinline__ uint32_t ex2b2(uint32_t x) {
    uint32_t y;
    asm("ex2.approx.ftz.bf16x2 %0, %1;" : "=r"(y) : "r"(x));
    return y;
}
__device__ __forceinline__ float bf2sum(uint32_t w) {
    float lo = __uint_as_float(w << 16);
    float hi = __uint_as_float(w & 0xffff0000u);
    return lo + hi;
}
__device__ __forceinline__ uint32_t scale_pack(uint32_t w, float s) {
    __nv_bfloat162 t = *reinterpret_cast<__nv_bfloat162*>(&w);
    return packbf(__bfloat162float(t.x)*s, __bfloat162float(t.y)*s);
}

__device__ __forceinline__ void mma_bf16(float& d0, float& d1, float& d2, float& d3,
                                         uint32_t a0, uint32_t a1, uint32_t a2, uint32_t a3,
                                         uint32_t b0, uint32_t b1) {
    asm volatile(
        "mma.sync.aligned.m16n8k16.row.col.f32.bf16.bf16.f32 "
        "{%0,%1,%2,%3}, {%4,%5,%6,%7}, {%8,%9}, {%0,%1,%2,%3};"
        : "+f"(d0), "+f"(d1), "+f"(d2), "+f"(d3)
        : "r"(a0), "r"(a1), "r"(a2), "r"(a3), "r"(b0), "r"(b1));
}

__device__ __forceinline__ void ldsm4(uint32_t& r0, uint32_t& r1, uint32_t& r2, uint32_t& r3,
                                      uint32_t addr) {
    asm volatile("ldmatrix.sync.aligned.m8n8.x4.shared.b16 {%0,%1,%2,%3}, [%4];"
        : "=r"(r0), "=r"(r1), "=r"(r2), "=r"(r3) : "r"(addr));
}

__device__ __forceinline__ void cp16h(__nv_bfloat16* dst, const __nv_bfloat16* src) {
    uint32_t d = (uint32_t)__cvta_generic_to_shared(dst);
    asm volatile("cp.async.cg.shared.global [%0], [%1], 16;" :: "r"(d), "l"(src));
}
#define CP_COMMIT()  asm volatile("cp.async.commit_group;" ::)
#define CP_WAIT2()   asm volatile("cp.async.wait_group 2;" ::)
#define CP_WAIT1()   asm volatile("cp.async.wait_group 1;" ::)
#define CP_WAIT0()   asm volatile("cp.async.wait_group 0;" ::)

// ---------------- fused: rmsnorm1 (blocks 0..Mrows) + weight convert --------
#define N2_Q   1572864
#define N2_O   524288
#define N2_S   32768
#define CONVBLKS 8576
__global__ __launch_bounds__(256) void conv_norm(
    const float* __restrict__ x, const float* __restrict__ n1w, __nv_bfloat16* __restrict__ o,
    const float* __restrict__ qkv_w, const float* __restrict__ o_w,
    const float* __restrict__ in_w, const float* __restrict__ gate_w,
    const float* __restrict__ out_w)
{
    if (blockIdx.x < Mrows) {
        int row = blockIdx.x;
        const float4* xr = (const float4*)(x + (size_t)row*Dv);
        float4 v = xr[threadIdx.x];
        float ss = v.x*v.x + v.y*v.y + v.z*v.z + v.w*v.w;
        #pragma unroll
        for (int off=16; off; off>>=1) ss += __shfl_xor_sync(0xffffffffu, ss, off);
        __shared__ float sm[8];
        int wid = threadIdx.x>>5, lane = threadIdx.x&31;
        if (lane==0) sm[wid] = ss;
        __syncthreads();
        float tot = sm[0]+sm[1]+sm[2]+sm[3]+sm[4]+sm[5]+sm[6]+sm[7];
        float scale = rsqrtf(tot*(1.0f/Dv) + EPSR);
        const float4* wr = (const float4*)n1w;
        float4 wv = wr[threadIdx.x];
        uint2 st = make_uint2(packbf(v.x*scale*wv.x, v.y*scale*wv.y),
                              packbf(v.z*scale*wv.z, v.w*scale*wv.w));
        *(uint2*)&o[(size_t)row*Dv + threadIdx.x*4] = st;
    } else {
        int i = (blockIdx.x - Mrows)*256 + threadIdx.x;
        const float* src; __nv_bfloat162* dst; int j;
        if (i < N2_Q)                        { src = qkv_w;  dst = (__nv_bfloat162*)g_wq;   j = i; }
        else if ((j = i - N2_Q) < N2_O)      { src = o_w;    dst = (__nv_bfloat162*)g_wo; }
        else if ((j = j - N2_O) < N2_S)      { src = in_w;   dst = (__nv_bfloat162*)g_wzg; }
        else if ((j = j - N2_S) < N2_S)      { src = gate_w; dst = (__nv_bfloat162*)g_wzg + N2_S; }
        else if ((j = j - N2_S) < N2_S)      { src = out_w;  dst = (__nv_bfloat162*)g_wout; }
        else return;
        float2 v = ((const float2*)src)[j];
        dst[j] = __floats2bfloat162_rn(v.x, v.y);
    }
}

// ---------------- RMSNorm -> bf16 ----------------
__global__ __launch_bounds__(256) void rmsnorm_kernel(
    const float* __restrict__ x, const float* __restrict__ w, __nv_bfloat16* __restrict__ o)
{
    int row = blockIdx.x;
    const float4* xr = (const float4*)(x + (size_t)row*Dv);
    float4 v = xr[threadIdx.x];
    float ss = v.x*v.x + v.y*v.y + v.z*v.z + v.w*v.w;
    #pragma unroll
    for (int off=16; off; off>>=1) ss += __shfl_xor_sync(0xffffffffu, ss, off);
    __shared__ float sm[8];
    int wid = threadIdx.x>>5, lane = threadIdx.x&31;
    if (lane==0) sm[wid] = ss;
    __syncthreads();
    float tot = sm[0]+sm[1]+sm[2]+sm[3]+sm[4]+sm[5]+sm[6]+sm[7];
    float scale = rsqrtf(tot*(1.0f/Dv) + EPSR);
    const float4* wr = (const float4*)w;
    float4 wv = wr[threadIdx.x];
    uint2 st = make_uint2(packbf(v.x*scale*wv.x, v.y*scale*wv.y),
                          packbf(v.z*scale*wv.z, v.w*scale*wv.w));
    *(uint2*)&o[(size_t)row*Dv + threadIdx.x*4] = st;
}

// ---------------- bf16 GEMM: 3-stage cp.async, split-K capable --------------
// modes: 0 fp32 (with split-K offset); 1 fp32+res; 2 bf16; 3 bf16 transposed; 4 fp32 silu
#define GLDH 40
#define GSTG (128*GLDH)
__global__ __launch_bounds__(256, 2) void gemm_bf16(
    const __nv_bfloat16* __restrict__ A, const __nv_bfloat16* __restrict__ W,
    const float* __restrict__ res, void* __restrict__ Cp, void* __restrict__ C2p,
    int M, int N, int nsplit, int K, int Kstride, int mode1, int mode2, int ld1, int ld2)
{
    extern __shared__ __nv_bfloat16 smg[];
    __nv_bfloat16* Asm = smg;
    __nv_bfloat16* Wsm = smg + 3*GSTG;

    const int tid = threadIdx.x;
    const int w   = tid >> 5;
    const int l   = tid & 31;
    const int g   = l >> 2;
    const int q   = l & 3;
    const int wm  = w >> 1;
    const int wn  = w & 1;
    const int bm  = blockIdx.y * 128;
    const int bn  = blockIdx.x * 128;

    const __nv_bfloat16* Ab = A + (size_t)blockIdx.z * K;
    const __nv_bfloat16* Wb = W + (size_t)blockIdx.z * K;

    const int lr = l & 7, lt = l >> 3;
    const uint32_t sAb = (uint32_t)__cvta_generic_to_shared(Asm);
    const uint32_t sWb = (uint32_t)__cvta_generic_to_shared(Wsm);
    const uint32_t aOff = (uint32_t)((((lt & 1)*8 + lr)*GLDH + (lt >> 1)*8) * 2);
    const uint32_t bOff = (uint32_t)((((lt >> 1)*8 + lr)*GLDH + (lt & 1)*8) * 2);

    const int crow = tid >> 2, cseg = (tid & 3) * 8;

    float c[2][8][4];
    #pragma unroll
    for (int i=0;i<2;i++)
        #pragma unroll
        for (int nj=0;nj<8;nj++)
            #pragma unroll
            for (int e=0;e<4;e++) c[i][nj][e] = 0.f;

    const int nch = K >> 5;

    #pragma unroll
    for (int p = 0; p < 2; p++) {
        #pragma unroll
        for (int ii = 0; ii < 2; ii++) {
            int row = crow + ii*64;
            cp16h(Asm + p*GSTG + row*GLDH + cseg, Ab + (size_t)(bm + row)*Kstride + p*32 + cseg);
            cp16h(Wsm + p*GSTG + row*GLDH + cseg, Wb + (size_t)(bn + row)*Kstride + p*32 + cseg);
        }
        CP_COMMIT();
    }

    for (int i = 0; i < nch; i++) {
        if (i == nch - 1) { CP_WAIT0(); } else { CP_WAIT1(); }
        __syncthreads();
        if (i + 2 < nch) {
            int st = (i + 2) % 3, kn = (i + 2) * 32;
            #pragma unroll
            for (int ii = 0; ii < 2; ii++) {
                int row = crow + ii*64;
                cp16h(Asm + st*GSTG + row*GLDH + cseg, Ab + (size_t)(bm + row)*Kstride + kn + cseg);
                cp16h(Wsm + st*GSTG + row*GLDH + cseg, Wb + (size_t)(bn + row)*Kstride + kn + cseg);
            }
            CP_COMMIT();
        }

        const uint32_t sa = sAb + (uint32_t)((i % 3) * GSTG * 2);
        const uint32_t sw = sWb + (uint32_t)((i % 3) * GSTG * 2);
        #pragma unroll
        for (int kc2 = 0; kc2 < 2; kc2++) {
            uint32_t a[2][4];
            #pragma unroll
            for (int ii = 0; ii < 2; ii++)
                ldsm4(a[ii][0], a[ii][1], a[ii][2], a[ii][3],
                      sa + aOff + (uint32_t)(((wm*32 + ii*16)*GLDH + kc2*16) * 2));
            uint32_t bfr[8][2];
            #pragma unroll
            for (int ncp = 0; ncp < 4; ncp++) {
                uint32_t x0, x1, x2, x3;
                ldsm4(x0, x1, x2, x3,
                      sw + bOff + (uint32_t)(((wn*64 + ncp*16)*GLDH + kc2*16) * 2));
                bfr[2*ncp][0] = x0; bfr[2*ncp][1] = x1;
                bfr[2*ncp+1][0] = x2; bfr[2*ncp+1][1] = x3;
            }
            #pragma unroll
            for (int ii = 0; ii < 2; ii++)
                #pragma unroll
                for (int nj = 0; nj < 8; nj++)
                    mma_bf16(c[ii][nj][0], c[ii][nj][1], c[ii][nj][2], c[ii][nj][3],
                             a[ii][0], a[ii][1], a[ii][2], a[ii][3], bfr[nj][0], bfr[nj][1]);
        }
    }

    #pragma unroll
    for (int i = 0; i < 2; i++) {
        #pragma unroll
        for (int nj = 0; nj < 8; nj++) {
            int row0 = bm + wm*32 + i*16 + g;
            int row1 = row0 + 8;
            int col  = bn + wn*64 + nj*8 + 2*q;
            bool first = (col < nsplit);
            int mode = first ? mode1 : mode2;
            float v0 = c[i][nj][0], v1 = c[i][nj][1], v2 = c[i][nj][2], v3 = c[i][nj][3];
            if (mode == 1) {
                v0 += res[(size_t)row0*N + col];
                v1 += res[(size_t)row0*N + col + 1];
                v2 += res[(size_t)row1*N + col];
                v3 += res[(size_t)row1*N + col + 1];
            } else if (mode == 4) {
                v0 = v0 / (1.f + __expf(-v0));
                v1 = v1 / (1.f + __expf(-v1));
                v2 = v2 / (1.f + __expf(-v2));
                v3 = v3 / (1.f + __expf(-v3));
            }
            if (mode == 2) {
                __nv_bfloat16* O = (__nv_bfloat16*)(first ? Cp : C2p);
                int ld = first ? ld1 : ld2;
                int cc = first ? col : col - nsplit;
                *(uint32_t*)&O[(size_t)row0*ld + cc] = packbf(v0, v1);
                *(uint32_t*)&O[(size_t)row1*ld + cc] = packbf(v2, v3);
            } else if (mode == 3) {
                __nv_bfloat16* O = (__nv_bfloat16*)C2p;
                int cc = col - nsplit;
                O[(size_t)cc*M + row0]     = __float2bfloat16(v0);
                O[(size_t)(cc+1)*M + row0] = __float2bfloat16(v1);
                O[(size_t)cc*M + row1]     = __float2bfloat16(v2);
                O[(size_t)(cc+1)*M + row1] = __float2bfloat16(v3);
            } else {
                float* O = (float*)(first ? Cp : C2p);
                int ld = first ? ld1 : ld2;
                int cc = first ? col : col - nsplit;
                if (mode == 0) O += (size_t)blockIdx.z * M * ld;
                *(float2*)&O[(size_t)row0*ld + cc] = make_float2(v0, v1);
                *(float2*)&O[(size_t)row1*ld + cc] = make_float2(v2, v3);
            }
        }
    }
}

// ---------------- fused z/gate reduce + Bi/Ci/dt, 256 CTAs (16 rows each) ----
__global__ __launch_bounds__(256) void bcd_fused(
    const float* __restrict__ Bp_w, const float* __restrict__ Cp_w,
    const float* __restrict__ dt_w, const float* __restrict__ dt_b,
    float* __restrict__ z, float* __restrict__ gate,
    float* __restrict__ Bi, float* __restrict__ Ci, float* __restrict__ dt)
{
    __shared__ float Zs[16*68];
    __shared__ float Wt[64*100];
    const int tid = threadIdx.x;
    const int bm = blockIdx.x*16;

    // reduce split-K partials for 16 rows x 128 cols
    for (int t = tid; t < 2048; t += 256) {
        int row = t >> 7, col = t & 127;
        float s = 0.f;
        #pragma unroll
        for (int p = 0; p < ZSPLIT; p++)
            s += g_zgacc[(size_t)p*Mrows*128 + (size_t)(bm + row)*128 + col];
        if (col < SCv) {
            Zs[row*68 + col] = s;
            z[(size_t)(bm + row)*SCv + col] = s;
        } else {
            gate[(size_t)(bm + row)*SCv + col - SCv] = s / (1.f + __expf(-s));
        }
    }
    for (int idx = tid; idx < 96*64; idx += 256) {
        int r = idx >> 6, c = idx & 63;
        float v = (r < 16) ? Bp_w[r*SCv + c] : (r < 32) ? Cp_w[(r-16)*SCv + c] : dt_w[(r-32)*SCv + c];
        Wt[c*100 + r] = v;
    }
    __syncthreads();

    const int ty = tid >> 4, tx = tid & 15;    // ty = row 0..15, tx -> 6 cols
    float acc[6];
    #pragma unroll
    for (int j=0;j<6;j++) acc[j] = 0.f;

    #pragma unroll 8
    for (int k = 0; k < 64; k++) {
        float a = Zs[ty*68 + k];
        #pragma unroll
        for (int j=0;j<6;j++) acc[j] = fmaf(a, Wt[k*100 + tx*6 + j], acc[j]);
    }

    int row = bm + ty;
    #pragma unroll
    for (int j=0;j<6;j++) {
        int c = tx*6 + j;
        float v = acc[j];
        if (c < 16) {
            Bi[(size_t)row*STv + c] = v;
        } else if (c < 32) {
            Ci[(size_t)row*STv + (c-16)] = v;
        } else {
            v += dt_b[c-32];
            dt[(size_t)row*SCv + (c-32)] = (v > 20.f) ? v : log1pf(__expf(v));
        }
    }
}

// ---------------- Flash attention v8b: prologue-first Q load ----------------
#define KS_LDH 72
#define STAGEH (64*KS_LDH*2)
__global__ __launch_bounds__(256, 2) void attn_mma_kernel(
    const __nv_bfloat16* __restrict__ qk, const __nv_bfloat16* __restrict__ vT,
    __nv_bfloat16* __restrict__ out)
{
    extern __shared__ __nv_bfloat16 smh[];

    const int tid = threadIdx.x;
    const int w   = tid >> 5;
    const int l   = tid & 31;
    const int g   = l >> 2;
    const int q   = l & 3;
    const int qb  = (int)gridDim.x - 1 - (int)blockIdx.x;
    const int h = blockIdx.y, b = blockIdx.z;
    const int qrow0 = qb*128 + w*16;

    const int lr = l & 7, lt = l >> 3;
    const uint32_t smbase = (uint32_t)__cvta_generic_to_shared(smh);
    const uint32_t bOff = (uint32_t)((((lt >> 1)*8 + lr)*KS_LDH + (lt & 1)*8) * 2);

    const int ntiles = 2*qb + 2;   // always even, >= 2

    // ---- issue prologue copies FIRST so DMA overlaps the Q loads ----
    #pragma unroll
    for (int p = 0; p < 4; p++) {
        if (p < ntiles) {
            __nv_bfloat16* Kb = smh + p*STAGEH;
            __nv_bfloat16* Vb = Kb + 64*KS_LDH;
            #pragma unroll
            for (int i = 0; i < 2; i++) {
                int idx = tid + i*256;
                int r = idx >> 3, seg = (idx & 7) * 8;
                cp16h(Kb + r*KS_LDH + seg, qk + ((size_t)(b*Tv + p*64 + r))*(2*Dv) + Dv + h*HDv + seg);
                cp16h(Vb + r*KS_LDH + seg, vT + ((size_t)(h*HDv + r))*Mrows + b*Tv + p*64 + seg);
            }
        }
        CP_COMMIT();
    }

    const float QSC = 0.125f * 1.4426950408889634f;
    uint32_t qa[4][4];
    {
        const uint32_t* Qw0 = (const uint32_t*)(qk + ((size_t)(b*Tv + qrow0 + g    ))*(2*Dv) + h*HDv);
        const uint32_t* Qw1 = (const uint32_t*)(qk + ((size_t)(b*Tv + qrow0 + g + 8))*(2*Dv) + h*HDv);
        #pragma unroll
        for (int kc = 0; kc < 4; kc++) {
            qa[kc][0] = scale_pack(Qw0[kc*8 + q    ], QSC);
            qa[kc][1] = scale_pack(Qw1[kc*8 + q    ], QSC);
            qa[kc][2] = scale_pack(Qw0[kc*8 + q + 4], QSC);
            qa[kc][3] = scale_pack(Qw1[kc*8 + q + 4], QSC);
        }
    }

    float o[8][4];
    #pragma unroll
    for (int nc = 0; nc < 8; nc++)
        #pragma unroll
        for (int e = 0; e < 4; e++) o[nc][e] = 0.f;
    float mA = -1e30f, mB = -1e30f, lA = 0.f, lB = 0.f;

    for (int kt = 0; kt < ntiles; kt += 2) {
        CP_WAIT2();
        __syncthreads();
        #pragma unroll
        for (int pp = 0; pp < 2; pp++) {
            int t = kt + 4 + pp;
            if (t < ntiles) {
                int st = t % 6;
                __nv_bfloat16* Kb = smh + st*STAGEH;
                __nv_bfloat16* Vb = Kb + 64*KS_LDH;
                #pragma unroll
                for (int i = 0; i < 2; i++) {
                    int idx = tid + i*256;
                    int r = idx >> 3, seg = (idx & 7) * 8;
                    cp16h(Kb + r*KS_LDH + seg, qk + ((size_t)(b*Tv + t*64 + r))*(2*Dv) + Dv + h*HDv + seg);
                    cp16h(Vb + r*KS_LDH + seg, vT + ((size_t)(h*HDv + r))*Mrows + b*Tv + t*64 + seg);
                }
            }
            CP_COMMIT();
        }

        #pragma unroll
        for (int sub = 0; sub < 2; sub++) {
            const int kti = kt + sub;
            const int kbase = kti*64;
            const uint32_t kst = smbase + (uint32_t)(((kti % 6)*STAGEH) * 2);
            const uint32_t vst = kst + (uint32_t)(64*KS_LDH*2);

            float s[8][4];
            #pragma unroll
            for (int nc = 0; nc < 8; nc++) {
                s[nc][0] = 0.f; s[nc][1] = 0.f; s[nc][2] = 0.f; s[nc][3] = 0.f;
            }
            #pragma unroll
            for (int ncp = 0; ncp < 4; ncp++) {
                #pragma unroll
                for (int kc = 0; kc < 4; kc++) {
                    uint32_t b0, b1, b2, b3;
                    ldsm4(b0, b1, b2, b3, kst + bOff + (uint32_t)(((ncp*16)*KS_LDH + kc*16) * 2));
                    mma_bf16(s[2*ncp][0], s[2*ncp][1], s[2*ncp][2], s[2*ncp][3],
                             qa[kc][0], qa[kc][1], qa[kc][2], qa[kc][3], b0, b1);
                    mma_bf16(s[2*ncp+1][0], s[2*ncp+1][1], s[2*ncp+1][2], s[2*ncp+1][3],
                             qa[kc][0], qa[kc][1], qa[kc][2], qa[kc][3], b2, b3);
                }
            }

            if (kbase + 63 > qrow0) {
                int rowA = qrow0 + g, rowB = qrow0 + g + 8;
                #pragma unroll
                for (int nc = 0; nc < 8; nc++) {
                    int c0 = kbase + nc*8 + 2*q, c1 = c0 + 1;
                    if (c0 > rowA) s[nc][0] = -1e30f;
                    if (c1 > rowA) s[nc][1] = -1e30f;
                    if (c0 > rowB) s[nc][2] = -1e30f;
                    if (c1 > rowB) s[nc][3] = -1e30f;
                }
            }

            float rmA = -1e30f, rmB = -1e30f;
            #pragma unroll
            for (int nc = 0; nc < 8; nc++) {
                rmA = fmaxf(rmA, fmaxf(s[nc][0], s[nc][1]));
                rmB = fmaxf(rmB, fmaxf(s[nc][2], s[nc][3]));
            }
            rmA = fmaxf(rmA, __shfl_xor_sync(0xffffffffu, rmA, 1));
            rmA = fmaxf(rmA, __shfl_xor_sync(0xffffffffu, rmA, 2));
            rmB = fmaxf(rmB, __shfl_xor_sync(0xffffffffu, rmB, 1));
            rmB = fmaxf(rmB, __shfl_xor_sync(0xffffffffu, rmB, 2));
            float mnA = fmaxf(mA, rmA), mnB = fmaxf(mB, rmB);
            float corrA = ex2(mA - mnA), corrB = ex2(mB - mnB);
            mA = mnA; mB = mnB;

            uint32_t pa[4][4];
            #pragma unroll
            for (int kc = 0; kc < 4; kc++) {
                pa[kc][0] = ex2b2(packbf(s[2*kc][0]   - mnA, s[2*kc][1]   - mnA));
                pa[kc][1] = ex2b2(packbf(s[2*kc][2]   - mnB, s[2*kc][3]   - mnB));
                pa[kc][2] = ex2b2(packbf(s[2*kc+1][0] - mnA, s[2*kc+1][1] - mnA));
                pa[kc][3] = ex2b2(packbf(s[2*kc+1][2] - mnB, s[2*kc+1][3] - mnB));
            }

            #pragma unroll
            for (int nc = 0; nc < 8; nc++) {
                o[nc][0] *= corrA; o[nc][1] *= corrA;
                o[nc][2] *= corrB; o[nc][3] *= corrB;
            }
            #pragma unroll
            for (int ncp = 0; ncp < 4; ncp++) {
                #pragma unroll
                for (int kc = 0; kc < 4; kc++) {
                    uint32_t v0, v1, v2, v3;
                    ldsm4(v0, v1, v2, v3, vst + bOff + (uint32_t)(((ncp*16)*KS_LDH + kc*16) * 2));
                    mma_bf16(o[2*ncp][0], o[2*ncp][1], o[2*ncp][2], o[2*ncp][3],
                             pa[kc][0], pa[kc][1], pa[kc][2], pa[kc][3], v0, v1);
                    mma_bf16(o[2*ncp+1][0], o[2*ncp+1][1], o[2*ncp+1][2], o[2*ncp+1][3],
                             pa[kc][0], pa[kc][1], pa[kc][2], pa[kc][3], v2, v3);
                }
            }

            float rsA = 0.f, rsB = 0.f;
            #pragma unroll
            for (int kc = 0; kc < 4; kc++) {
                rsA += bf2sum(pa[kc][0]) + bf2sum(pa[kc][2]);
                rsB += bf2sum(pa[kc][1]) + bf2sum(pa[kc][3]);
            }
            rsA += __shfl_xor_sync(0xffffffffu, rsA, 1);
            rsA += __shfl_xor_sync(0xffffffffu, rsA, 2);
            rsB += __shfl_xor_sync(0xffffffffu, rsB, 1);
            rsB += __shfl_xor_sync(0xffffffffu, rsB, 2);
            lA = lA*corrA + rsA;
            lB = lB*corrB + rsB;
        }
    }

    float invA = 1.f / lA, invB = 1.f / lB;
    __nv_bfloat16* ob0 = out + ((size_t)(b*Tv + qrow0 + g    ))*Dv + h*HDv;
    __nv_bfloat16* ob1 = out + ((size_t)(b*Tv + qrow0 + g + 8))*Dv + h*HDv;
    #pragma unroll
    for (int nc = 0; nc < 8; nc++) {
        int c = nc*8 + 2*q;
        *(uint32_t*)&ob0[c] = packbf(o[nc][0]*invA, o[nc][1]*invA);
        *(uint32_t*)&ob1[c] = packbf(o[nc][2]*invB, o[nc][3]*invB);
    }
}

// ---------------- Parallel selective scan (CH=64) ----------------
__global__ __launch_bounds__(256) void scan_phase1(
    const float* __restrict__ dt, const float* __restrict__ z,
    const float* __restrict__ Bi, const float* __restrict__ A_log)
{
    int gth = blockIdx.x*256 + threadIdx.x;
    int chan = gth & 127, chunk = gth >> 7;
    int b = chan >> 6, sc = chan & 63;
    float A[16];
    #pragma unroll
    for (int st = 0; st < 16; st++) A[st] = -__expf(A_log[sc*STv + st]);
    float aP[16], bP[16];
    #pragma unroll
    for (int st = 0; st < 16; st++) { aP[st] = 1.f; bP[st] = 0.f; }
    int t0 = chunk*TSTEP;
    const float* dtp = dt + ((size_t)b*Tv + t0)*SCv + sc;
    const float* zp  = z  + ((size_t)b*Tv + t0)*SCv + sc;
    const float* Bp  = Bi + ((size_t)b*Tv + t0)*STv;
    for (int tt = 0; tt < TSTEP; tt++) {
        float dtc = dtp[(size_t)tt*SCv];
        float zc  = zp [(size_t)tt*SCv];
        float dz  = dtc*zc;
        float4 B0 = *(const float4*)&Bp[tt*STv + 0];
        float4 B1 = *(const float4*)&Bp[tt*STv + 4];
        float4 B2 = *(const float4*)&Bp[tt*STv + 8];
        float4 B3 = *(const float4*)&Bp[tt*STv + 12];
        float Bvv[16] = {B0.x,B0.y,B0.z,B0.w, B1.x,B1.y,B1.z,B1.w,
                         B2.x,B2.y,B2.z,B2.w, B3.x,B3.y,B3.z,B3.w};
        #pragma unroll
        for (int st = 0; st < 16; st++) {
            float ab = fmaf(dtc, A[st], 1.f);
            aP[st] *= ab;
            bP[st] = fmaf(ab, bP[st], dz*Bvv[st]);
        }
    }
    int base = (chan*CH + chunk)*16;
    #pragma unroll
    for (int st = 0; st < 16; st++) { g_scanA[base+st] = aP[st]; g_scanB[base+st] = bP[st]; }
}

__global__ __launch_bounds__(256) void scan_phase2()
{
    int gth = blockIdx.x*256 + threadIdx.x;
    int chan = gth >> 4, st = gth & 15;
    int base = chan*CH*16 + st;
    float s = 0.f;
    float a = g_scanA[base], bq = g_scanB[base];
    #pragma unroll 8
    for (int ch = 0; ch < CH; ch++) {
        int idx = base + ch*16;
        float an = 0.f, bn = 0.f;
        if (ch + 1 < CH) { an = g_scanA[idx + 16]; bn = g_scanB[idx + 16]; }
        g_scanS[idx] = s;
        s = fmaf(a, s, bq);
        a = an; bq = bn;
    }
}

__global__ __launch_bounds__(256) void scan_phase3(
    const float* __restrict__ dt, const float* __restrict__ z,
    const float* __restrict__ Bi, const float* __restrict__ Ci,
    const float* __restrict__ gate, const float* __restrict__ A_log,
    __nv_bfloat16* __restrict__ y)
{
    int gth = blockIdx.x*256 + threadIdx.x;
    int chan = gth & 127, chunk = gth >> 7;
    int b = chan >> 6, sc = chan & 63;
    float A[16];
    #pragma unroll
    for (int st = 0; st < 16; st++) A[st] = -__expf(A_log[sc*STv + st]);
    float state[16];
    {
        int base = (chan*CH + chunk)*16;
        #pragma unroll
        for (int st = 0; st < 16; st++) state[st] = g_scanS[base+st];
    }
    int t0 = chunk*TSTEP;
    const float* dtp = dt   + ((size_t)b*Tv + t0)*SCv + sc;
    const float* zp  = z    + ((size_t)b*Tv + t0)*SCv + sc;
    const float* gp  = gate + ((size_t)b*Tv + t0)*SCv + sc;
    const float* Bp  = Bi + ((size_t)b*Tv + t0)*STv;
    const float* Cp  = Ci + ((size_t)b*Tv + t0)*STv;
    __nv_bfloat16* yp = y + ((size_t)b*Tv + t0)*SCv + sc;
    for (int tt = 0; tt < TSTEP; tt++) {
        float dtc = dtp[(size_t)tt*SCv];
        float zc  = zp [(size_t)tt*SCv];
        float dz  = dtc*zc;
        float4 B0 = *(const float4*)&Bp[tt*STv + 0];
        float4 B1 = *(const float4*)&Bp[tt*STv + 4];
        float4 B2 = *(const float4*)&Bp[tt*STv + 8];
        float4 B3 = *(const float4*)&Bp[tt*STv + 12];
        float4 C0 = *(const float4*)&Cp[tt*STv + 0];
        float4 C1 = *(const float4*)&Cp[tt*STv + 4];
        float4 C2 = *(const float4*)&Cp[tt*STv + 8];
        float4 C3 = *(const float4*)&Cp[tt*STv + 12];
        float Bvv[16] = {B0.x,B0.y,B0.z,B0.w, B1.x,B1.y,B1.z,B1.w,
                         B2.x,B2.y,B2.z,B2.w, B3.x,B3.y,B3.z,B3.w};
        float Cvv[16] = {C0.x,C0.y,C0.z,C0.w, C1.x,C1.y,C1.z,C1.w,
                         C2.x,C2.y,C2.z,C2.w, C3.x,C3.y,C3.z,C3.w};
        float p0 = 0.f, p1 = 0.f, p2 = 0.f, p3 = 0.f;
        #pragma unroll
        for (int st = 0; st < 16; st += 4) {
            float ab;
            ab = fmaf(dtc, A[st+0], 1.f); state[st+0] = fmaf(ab, state[st+0], dz*Bvv[st+0]); p0 = fmaf(state[st+0], Cvv[st+0], p0);
            ab = fmaf(dtc, A[st+1], 1.f); state[st+1] = fmaf(ab, state[st+1], dz*Bvv[st+1]); p1 = fmaf(state[st+1], Cvv[st+1], p1);
            ab = fmaf(dtc, A[st+2], 1.f); state[st+2] = fmaf(ab, state[st+2], dz*Bvv[st+2]); p2 = fmaf(state[st+2], Cvv[st+2], p2);
            ab = fmaf(dtc, A[st+3], 1.f); state[st+3] = fmaf(ab, state[st+3], dz*Bvv[st+3]); p3 = fmaf(state[st+3], Cvv[st+3], p3);
        }
        float p = (p0 + p1) + (p2 + p3);
        yp[(size_t)tt*SCv] = __float2bfloat16(p * gp[(size_t)tt*SCv]);
    }
}

// ---------------- launch ----------------
extern "C" void kernel_launch(void* const* d_in, const int* in_sizes, int n_in,
                              void* d_out, int out_size)
{
    const float* x      = (const float*)d_in[0];
    const float* qkv_w  = (const float*)d_in[1];
    const float* o_w    = (const float*)d_in[2];
    const float* n1w    = (const float*)d_in[3];
    const float* n2w    = (const float*)d_in[4];
    const float* in_w   = (const float*)d_in[5];
    const float* out_w  = (const float*)d_in[6];
    const float* A_log  = (const float*)d_in[7];
    const float* Bp_w   = (const float*)d_in[8];
    const float* Cp_w   = (const float*)d_in[9];
    const float* dt_w   = (const float*)d_in[10];
    const float* dt_b   = (const float*)d_in[11];
    const float* gate_w = (const float*)d_in[12];
    float* out = (float*)d_out;

    __nv_bfloat16 *hb,*qkb,*vTb,*attnb,*h2b,*yb16,*wq,*wo,*wzg,*wout;
    float *x1,*zb,*gateb,*Bib,*Cib,*dtb,*zgacc;
    cudaGetSymbolAddress((void**)&hb,   g_h);
    cudaGetSymbolAddress((void**)&qkb,  g_qk);
    cudaGetSymbolAddress((void**)&vTb,  g_vT);
    cudaGetSymbolAddress((void**)&attnb,g_attn);
    cudaGetSymbolAddress((void**)&x1,   g_x1);
    cudaGetSymbolAddress((void**)&h2b,  g_h2);
    cudaGetSymbolAddress((void**)&zb,   g_z);
    cudaGetSymbolAddress((void**)&gateb,g_gate);
    cudaGetSymbolAddress((void**)&Bib,  g_Bi);
    cudaGetSymbolAddress((void**)&Cib,  g_Ci);
    cudaGetSymbolAddress((void**)&dtb,  g_dt);
    cudaGetSymbolAddress((void**)&yb16, g_y);
    cudaGetSymbolAddress((void**)&zgacc,g_zgacc);
    cudaGetSymbolAddress((void**)&wq,   g_wq);
    cudaGetSymbolAddress((void**)&wo,   g_wo);
    cudaGetSymbolAddress((void**)&wzg,  g_wzg);
    cudaGetSymbolAddress((void**)&wout, g_wout);

    const int gemm_smem = 6*GSTG*2;     // 61440 B
    const int attn_smem = 6*STAGEH*2;   // 110592 B
    cudaFuncSetAttribute(gemm_bf16, cudaFuncAttributeMaxDynamicSharedMemorySize, gemm_smem);
    cudaFuncSetAttribute(attn_mma_kernel, cudaFuncAttributeMaxDynamicSharedMemorySize, attn_smem);

    // 0. fused rmsnorm1 + weight convert
    conv_norm<<<Mrows + CONVBLKS, 256>>>(x, n1w, hb, qkv_w, o_w, in_w, gate_w, out_w);
    // 1. qkv: Q,K -> g_qk (bf16), V -> g_vT (transposed bf16)
    gemm_bf16<<<dim3(24, 32), 256, gemm_smem>>>(hb, wq, nullptr, qkb, vTb,
                                     Mrows, 3*Dv, 2*Dv, Dv, Dv, 2, 3, 2*Dv, 0);
    // 2. attention -> bf16
    attn_mma_kernel<<<dim3(Tv/128, Hv, Bv), 256, attn_smem>>>(qkb, vTb, attnb);
    // 3. x1 = x + attn @ o_w^T (fp32)
    gemm_bf16<<<dim3(8, 32), 256, gemm_smem>>>(attnb, wo, x, x1, nullptr,
                                    Mrows, Dv, Dv, Dv, Dv, 1, 1, Dv, 0);
    // 4. rmsnorm2 -> bf16
    rmsnorm_kernel<<<Mrows, 256>>>(x1, n2w, h2b);
    // 5. z/gate split-K (4 splits of K=256) -> partials
    gemm_bf16<<<dim3(1, 32, ZSPLIT), 256, gemm_smem>>>(h2b, wzg, nullptr, zgacc, nullptr,
                                    Mrows, 2*SCv, 2*SCv, Dv/ZSPLIT, Dv, 0, 0, 2*SCv, 0);
    // 6. fused reduce + Bi/Ci/dt (256 CTAs)
    bcd_fused<<<256, 256>>>(Bp_w, Cp_w, dt_w, dt_b, zb, gateb, Bib, Cib, dtb);
    // 7. parallel scan -> y bf16
    scan_phase1<<<32, 256>>>(dtb, zb, Bib, A_log);
    scan_phase2<<<8, 256>>>();
    scan_phase3<<<32, 256>>>(dtb, zb, Bib, Cib, gateb, A_log, yb16);
    // 8. out = x1 + y @ out_w^T (fp32)
    gemm_bf16<<<dim3(8, 32), 256, gemm_smem>>>(yb16, wout, x1, out, nullptr,
                                    Mrows, Dv, Dv, SCv, SCv, 1, 1, Dv, 0);
}

// round 16
// speedup vs baseline: 1.1050x; 1.0304x over previous
#include <cuda_runtime.h>
#include <cuda_bf16.h>
#include <math.h>
#include <cstdint>

#define Bv 2
#define Tv 2048
#define Dv 1024
#define Hv 16
#define HDv 64
#define SCv 64
#define STv 16
#define Mrows (Bv*Tv)   // 4096
#define EPSR 1.1920929e-07f
#define CH 64
#define TSTEP (Tv/CH)   // 32
#define ZSPLIT 4

// ---------------- scratch (device globals) ----------------
__device__ __nv_bfloat16 g_h   [Mrows*Dv];
__device__ __nv_bfloat16 g_qk  [Mrows*2*Dv];
__device__ __nv_bfloat16 g_vT  [Dv*Mrows];
__device__ __nv_bfloat16 g_attn[Mrows*Dv];
__device__ float         g_x1  [Mrows*Dv];
__device__ __nv_bfloat16 g_h2  [Mrows*Dv];
__device__ float g_z   [Mrows*SCv];
__device__ float g_gate[Mrows*SCv];
__device__ float g_Bi  [Mrows*STv];
__device__ float g_Ci  [Mrows*STv];
__device__ float g_dt  [Mrows*SCv];
__device__ __nv_bfloat16 g_y [Mrows*SCv];
__device__ float g_scanA[128*CH*16];
__device__ float g_scanB[128*CH*16];
__device__ float g_scanS[128*CH*16];
__device__ float g_zgacc[ZSPLIT*Mrows*128];
__device__ __nv_bfloat16 g_wq  [3*Dv*Dv];
__device__ __nv_bfloat16 g_wo  [Dv*Dv];
__device__ __nv_bfloat16 g_wzg [2*SCv*Dv];
__device__ __nv_bfloat16 g_wout[Dv*SCv];

__device__ __forceinline__ uint32_t packbf(float a, float b) {
    __nv_bfloat162 t = __floats2bfloat162_rn(a, b);
    return *reinterpret_cast<uint32_t*>(&t);
}
__device__ __forceinline__ float ex2(float x) {
    float y;
    asm("ex2.approx.f32 %0, %1;" : "=f"(y) : "f"(x));
    return y;
}
__device__ __forceinline__ uint32_t ex2b2(uint32_t x) {
    uint32_t y;
    asm("ex2.approx.ftz.bf16x2 %0, %1;" : "=r"(y) : "r"(x));
    return y;
}
__device__ __forceinline__ float bf2sum(uint32_t w) {
    float lo = __uint_as_float(w << 16);
    float hi = __uint_as_float(w & 0xffff0000u);
    return lo + hi;
}
__device__ __forceinline__ uint32_t scale_pack(uint32_t w, float s) {
    __nv_bfloat162 t = *reinterpret_cast<__nv_bfloat162*>(&w);
    return packbf(__bfloat162float(t.x)*s, __bfloat162float(t.y)*s);
}

__device__ __forceinline__ void mma_bf16(float& d0, float& d1, float& d2, float& d3,
                                         uint32_t a0, uint32_t a1, uint32_t a2, uint32_t a3,
                                         uint32_t b0, uint32_t b1) {
    asm volatile(
        "mma.sync.aligned.m16n8k16.row.col.f32.bf16.bf16.f32 "
        "{%0,%1,%2,%3}, {%4,%5,%6,%7}, {%8,%9}, {%0,%1,%2,%3};"
        : "+f"(d0), "+f"(d1), "+f"(d2), "+f"(d3)
        : "r"(a0), "r"(a1), "r"(a2), "r"(a3), "r"(b0), "r"(b1));
}

__device__ __forceinline__ void ldsm4(uint32_t& r0, uint32_t& r1, uint32_t& r2, uint32_t& r3,
                                      uint32_t addr) {
    asm volatile("ldmatrix.sync.aligned.m8n8.x4.shared.b16 {%0,%1,%2,%3}, [%4];"
        : "=r"(r0), "=r"(r1), "=r"(r2), "=r"(r3) : "r"(addr));
}

__device__ __forceinline__ void cp16h(__nv_bfloat16* dst, const __nv_bfloat16* src) {
    uint32_t d = (uint32_t)__cvta_generic_to_shared(dst);
    asm volatile("cp.async.cg.shared.global [%0], [%1], 16;" :: "r"(d), "l"(src));
}
#define CP_COMMIT()  asm volatile("cp.async.commit_group;" ::)
#define CP_WAIT2()   asm volatile("cp.async.wait_group 2;" ::)
#define CP_WAIT1()   asm volatile("cp.async.wait_group 1;" ::)
#define CP_WAIT0()   asm volatile("cp.async.wait_group 0;" ::)

// ---------------- fused: rmsnorm1 (blocks 0..Mrows) + weight convert --------
#define N2_Q   1572864
#define N2_O   524288
#define N2_S   32768
#define CONVBLKS 8576
__global__ __launch_bounds__(256) void conv_norm(
    const float* __restrict__ x, const float* __restrict__ n1w, __nv_bfloat16* __restrict__ o,
    const float* __restrict__ qkv_w, const float* __restrict__ o_w,
    const float* __restrict__ in_w, const float* __restrict__ gate_w,
    const float* __restrict__ out_w)
{
    if (blockIdx.x < Mrows) {
        int row = blockIdx.x;
        const float4* xr = (const float4*)(x + (size_t)row*Dv);
        float4 v = xr[threadIdx.x];
        float ss = v.x*v.x + v.y*v.y + v.z*v.z + v.w*v.w;
        #pragma unroll
        for (int off=16; off; off>>=1) ss += __shfl_xor_sync(0xffffffffu, ss, off);
        __shared__ float sm[8];
        int wid = threadIdx.x>>5, lane = threadIdx.x&31;
        if (lane==0) sm[wid] = ss;
        __syncthreads();
        float tot = sm[0]+sm[1]+sm[2]+sm[3]+sm[4]+sm[5]+sm[6]+sm[7];
        float scale = rsqrtf(tot*(1.0f/Dv) + EPSR);
        const float4* wr = (const float4*)n1w;
        float4 wv = wr[threadIdx.x];
        uint2 st = make_uint2(packbf(v.x*scale*wv.x, v.y*scale*wv.y),
                              packbf(v.z*scale*wv.z, v.w*scale*wv.w));
        *(uint2*)&o[(size_t)row*Dv + threadIdx.x*4] = st;
    } else {
        int i = (blockIdx.x - Mrows)*256 + threadIdx.x;
        const float* src; __nv_bfloat162* dst; int j;
        if (i < N2_Q)                        { src = qkv_w;  dst = (__nv_bfloat162*)g_wq;   j = i; }
        else if ((j = i - N2_Q) < N2_O)      { src = o_w;    dst = (__nv_bfloat162*)g_wo; }
        else if ((j = j - N2_O) < N2_S)      { src = in_w;   dst = (__nv_bfloat162*)g_wzg; }
        else if ((j = j - N2_S) < N2_S)      { src = gate_w; dst = (__nv_bfloat162*)g_wzg + N2_S; }
        else if ((j = j - N2_S) < N2_S)      { src = out_w;  dst = (__nv_bfloat162*)g_wout; }
        else return;
        float2 v = ((const float2*)src)[j];
        dst[j] = __floats2bfloat162_rn(v.x, v.y);
    }
}

// ---------------- RMSNorm -> bf16 ----------------
__global__ __launch_bounds__(256) void rmsnorm_kernel(
    const float* __restrict__ x, const float* __restrict__ w, __nv_bfloat16* __restrict__ o)
{
    int row = blockIdx.x;
    const float4* xr = (const float4*)(x + (size_t)row*Dv);
    float4 v = xr[threadIdx.x];
    float ss = v.x*v.x + v.y*v.y + v.z*v.z + v.w*v.w;
    #pragma unroll
    for (int off=16; off; off>>=1) ss += __shfl_xor_sync(0xffffffffu, ss, off);
    __shared__ float sm[8];
    int wid = threadIdx.x>>5, lane = threadIdx.x&31;
    if (lane==0) sm[wid] = ss;
    __syncthreads();
    float tot = sm[0]+sm[1]+sm[2]+sm[3]+sm[4]+sm[5]+sm[6]+sm[7];
    float scale = rsqrtf(tot*(1.0f/Dv) + EPSR);
    const float4* wr = (const float4*)w;
    float4 wv = wr[threadIdx.x];
    uint2 st = make_uint2(packbf(v.x*scale*wv.x, v.y*scale*wv.y),
                          packbf(v.z*scale*wv.z, v.w*scale*wv.w));
    *(uint2*)&o[(size_t)row*Dv + threadIdx.x*4] = st;
}

// ---------------- bf16 GEMM v3: 64-wide K chunks, 3-stage, split-K ----------
// modes: 0 fp32 (with split-K offset); 1 fp32+res; 2 bf16; 3 bf16 transposed; 4 fp32 silu
#define GLDH 72
#define GSTG (128*GLDH)
__global__ __launch_bounds__(256, 2) void gemm_bf16(
    const __nv_bfloat16* __restrict__ A, const __nv_bfloat16* __restrict__ W,
    const float* __restrict__ res, void* __restrict__ Cp, void* __restrict__ C2p,
    int M, int N, int nsplit, int K, int Kstride, int mode1, int mode2, int ld1, int ld2)
{
    extern __shared__ __nv_bfloat16 smg[];
    __nv_bfloat16* Asm = smg;
    __nv_bfloat16* Wsm = smg + 3*GSTG;

    const int tid = threadIdx.x;
    const int w   = tid >> 5;
    const int l   = tid & 31;
    const int g   = l >> 2;
    const int q   = l & 3;
    const int wm  = w >> 1;
    const int wn  = w & 1;
    const int bm  = blockIdx.y * 128;
    const int bn  = blockIdx.x * 128;

    const __nv_bfloat16* Ab = A + (size_t)blockIdx.z * K;
    const __nv_bfloat16* Wb = W + (size_t)blockIdx.z * K;

    const int lr = l & 7, lt = l >> 3;
    const uint32_t sAb = (uint32_t)__cvta_generic_to_shared(Asm);
    const uint32_t sWb = (uint32_t)__cvta_generic_to_shared(Wsm);
    const uint32_t aOff = (uint32_t)((((lt & 1)*8 + lr)*GLDH + (lt >> 1)*8) * 2);
    const uint32_t bOff = (uint32_t)((((lt >> 1)*8 + lr)*GLDH + (lt & 1)*8) * 2);

    float c[2][8][4];
    #pragma unroll
    for (int i=0;i<2;i++)
        #pragma unroll
        for (int nj=0;nj<8;nj++)
            #pragma unroll
            for (int e=0;e<4;e++) c[i][nj][e] = 0.f;

    const int nch = K >> 6;    // 64-wide chunks

    // prologue: stages 0,1 (guarded for short K)
    #pragma unroll
    for (int p = 0; p < 2; p++) {
        if (p < nch) {
            #pragma unroll
            for (int ii = 0; ii < 4; ii++) {
                int idx = tid + ii*256;          // 0..1023
                int row = idx >> 3, seg = (idx & 7) * 8;
                cp16h(Asm + p*GSTG + row*GLDH + seg, Ab + (size_t)(bm + row)*Kstride + p*64 + seg);
                cp16h(Wsm + p*GSTG + row*GLDH + seg, Wb + (size_t)(bn + row)*Kstride + p*64 + seg);
            }
        }
        CP_COMMIT();
    }

    for (int i = 0; i < nch; i++) {
        if (i == nch - 1) { CP_WAIT0(); } else { CP_WAIT1(); }
        __syncthreads();
        if (i + 2 < nch) {
            int st = (i + 2) % 3, kn = (i + 2) * 64;
            #pragma unroll
            for (int ii = 0; ii < 4; ii++) {
                int idx = tid + ii*256;
                int row = idx >> 3, seg = (idx & 7) * 8;
                cp16h(Asm + st*GSTG + row*GLDH + seg, Ab + (size_t)(bm + row)*Kstride + kn + seg);
                cp16h(Wsm + st*GSTG + row*GLDH + seg, Wb + (size_t)(bn + row)*Kstride + kn + seg);
            }
            CP_COMMIT();
        }

        const uint32_t sa = sAb + (uint32_t)((i % 3) * GSTG * 2);
        const uint32_t sw = sWb + (uint32_t)((i % 3) * GSTG * 2);
        #pragma unroll
        for (int kc2 = 0; kc2 < 4; kc2++) {
            uint32_t a[2][4];
            #pragma unroll
            for (int ii = 0; ii < 2; ii++)
                ldsm4(a[ii][0], a[ii][1], a[ii][2], a[ii][3],
                      sa + aOff + (uint32_t)(((wm*32 + ii*16)*GLDH + kc2*16) * 2));
            uint32_t bfr[8][2];
            #pragma unroll
            for (int ncp = 0; ncp < 4; ncp++) {
                uint32_t x0, x1, x2, x3;
                ldsm4(x0, x1, x2, x3,
                      sw + bOff + (uint32_t)(((wn*64 + ncp*16)*GLDH + kc2*16) * 2));
                bfr[2*ncp][0] = x0; bfr[2*ncp][1] = x1;
                bfr[2*ncp+1][0] = x2; bfr[2*ncp+1][1] = x3;
            }
            #pragma unroll
            for (int ii = 0; ii < 2; ii++)
                #pragma unroll
                for (int nj = 0; nj < 8; nj++)
                    mma_bf16(c[ii][nj][0], c[ii][nj][1], c[ii][nj][2], c[ii][nj][3],
                             a[ii][0], a[ii][1], a[ii][2], a[ii][3], bfr[nj][0], bfr[nj][1]);
        }
    }

    #pragma unroll
    for (int i = 0; i < 2; i++) {
        #pragma unroll
        for (int nj = 0; nj < 8; nj++) {
            int row0 = bm + wm*32 + i*16 + g;
            int row1 = row0 + 8;
            int col  = bn + wn*64 + nj*8 + 2*q;
            bool first = (col < nsplit);
            int mode = first ? mode1 : mode2;
            float v0 = c[i][nj][0], v1 = c[i][nj][1], v2 = c[i][nj][2], v3 = c[i][nj][3];
            if (mode == 1) {
                v0 += res[(size_t)row0*N + col];
                v1 += res[(size_t)row0*N + col + 1];
                v2 += res[(size_t)row1*N + col];
                v3 += res[(size_t)row1*N + col + 1];
            } else if (mode == 4) {
                v0 = v0 / (1.f + __expf(-v0));
                v1 = v1 / (1.f + __expf(-v1));
                v2 = v2 / (1.f + __expf(-v2));
                v3 = v3 / (1.f + __expf(-v3));
            }
            if (mode == 2) {
                __nv_bfloat16* O = (__nv_bfloat16*)(first ? Cp : C2p);
                int ld = first ? ld1 : ld2;
                int cc = first ? col : col - nsplit;
                *(uint32_t*)&O[(size_t)row0*ld + cc] = packbf(v0, v1);
                *(uint32_t*)&O[(size_t)row1*ld + cc] = packbf(v2, v3);
            } else if (mode == 3) {
                __nv_bfloat16* O = (__nv_bfloat16*)C2p;
                int cc = col - nsplit;
                O[(size_t)cc*M + row0]     = __float2bfloat16(v0);
                O[(size_t)(cc+1)*M + row0] = __float2bfloat16(v1);
                O[(size_t)cc*M + row1]     = __float2bfloat16(v2);
                O[(size_t)(cc+1)*M + row1] = __float2bfloat16(v3);
            } else {
                float* O = (float*)(first ? Cp : C2p);
                int ld = first ? ld1 : ld2;
                int cc = first ? col : col - nsplit;
                if (mode == 0) O += (size_t)blockIdx.z * M * ld;
                *(float2*)&O[(size_t)row0*ld + cc] = make_float2(v0, v1);
                *(float2*)&O[(size_t)row1*ld + cc] = make_float2(v2, v3);
            }
        }
    }
}

// ---------------- fused z/gate reduce + Bi/Ci/dt, 256 CTAs (16 rows each) ----
__global__ __launch_bounds__(256) void bcd_fused(
    const float* __restrict__ Bp_w, const float* __restrict__ Cp_w,
    const float* __restrict__ dt_w, const float* __restrict__ dt_b,
    float* __restrict__ z, float* __restrict__ gate,
    float* __restrict__ Bi, float* __restrict__ Ci, float* __restrict__ dt)
{
    __shared__ float Zs[16*68];
    __shared__ float Wt[64*100];
    const int tid = threadIdx.x;
    const int bm = blockIdx.x*16;

    for (int t = tid; t < 2048; t += 256) {
        int row = t >> 7, col = t & 127;
        float s = 0.f;
        #pragma unroll
        for (int p = 0; p < ZSPLIT; p++)
            s += g_zgacc[(size_t)p*Mrows*128 + (size_t)(bm + row)*128 + col];
        if (col < SCv) {
            Zs[row*68 + col] = s;
            z[(size_t)(bm + row)*SCv + col] = s;
        } else {
            gate[(size_t)(bm + row)*SCv + col - SCv] = s / (1.f + __expf(-s));
        }
    }
    for (int idx = tid; idx < 96*64; idx += 256) {
        int r = idx >> 6, c = idx & 63;
        float v = (r < 16) ? Bp_w[r*SCv + c] : (r < 32) ? Cp_w[(r-16)*SCv + c] : dt_w[(r-32)*SCv + c];
        Wt[c*100 + r] = v;
    }
    __syncthreads();

    const int ty = tid >> 4, tx = tid & 15;
    float acc[6];
    #pragma unroll
    for (int j=0;j<6;j++) acc[j] = 0.f;

    #pragma unroll 8
    for (int k = 0; k < 64; k++) {
        float a = Zs[ty*68 + k];
        #pragma unroll
        for (int j=0;j<6;j++) acc[j] = fmaf(a, Wt[k*100 + tx*6 + j], acc[j]);
    }

    int row = bm + ty;
    #pragma unroll
    for (int j=0;j<6;j++) {
        int c = tx*6 + j;
        float v = acc[j];
        if (c < 16) {
            Bi[(size_t)row*STv + c] = v;
        } else if (c < 32) {
            Ci[(size_t)row*STv + (c-16)] = v;
        } else {
            v += dt_b[c-32];
            dt[(size_t)row*SCv + (c-32)] = (v > 20.f) ? v : log1pf(__expf(v));
        }
    }
}

// ---------------- Flash attention v8b ----------------
#define KS_LDH 72
#define STAGEH (64*KS_LDH*2)
__global__ __launch_bounds__(256, 2) void attn_mma_kernel(
    const __nv_bfloat16* __restrict__ qk, const __nv_bfloat16* __restrict__ vT,
    __nv_bfloat16* __restrict__ out)
{
    extern __shared__ __nv_bfloat16 smh[];

    const int tid = threadIdx.x;
    const int w   = tid >> 5;
    const int l   = tid & 31;
    const int g   = l >> 2;
    const int q   = l & 3;
    const int qb  = (int)gridDim.x - 1 - (int)blockIdx.x;
    const int h = blockIdx.y, b = blockIdx.z;
    const int qrow0 = qb*128 + w*16;

    const int lr = l & 7, lt = l >> 3;
    const uint32_t smbase = (uint32_t)__cvta_generic_to_shared(smh);
    const uint32_t bOff = (uint32_t)((((lt >> 1)*8 + lr)*KS_LDH + (lt & 1)*8) * 2);

    const int ntiles = 2*qb + 2;

    #pragma unroll
    for (int p = 0; p < 4; p++) {
        if (p < ntiles) {
            __nv_bfloat16* Kb = smh + p*STAGEH;
            __nv_bfloat16* Vb = Kb + 64*KS_LDH;
            #pragma unroll
            for (int i = 0; i < 2; i++) {
                int idx = tid + i*256;
                int r = idx >> 3, seg = (idx & 7) * 8;
                cp16h(Kb + r*KS_LDH + seg, qk + ((size_t)(b*Tv + p*64 + r))*(2*Dv) + Dv + h*HDv + seg);
                cp16h(Vb + r*KS_LDH + seg, vT + ((size_t)(h*HDv + r))*Mrows + b*Tv + p*64 + seg);
            }
        }
        CP_COMMIT();
    }

    const float QSC = 0.125f * 1.4426950408889634f;
    uint32_t qa[4][4];
    {
        const uint32_t* Qw0 = (const uint32_t*)(qk + ((size_t)(b*Tv + qrow0 + g    ))*(2*Dv) + h*HDv);
        const uint32_t* Qw1 = (const uint32_t*)(qk + ((size_t)(b*Tv + qrow0 + g + 8))*(2*Dv) + h*HDv);
        #pragma unroll
        for (int kc = 0; kc < 4; kc++) {
            qa[kc][0] = scale_pack(Qw0[kc*8 + q    ], QSC);
            qa[kc][1] = scale_pack(Qw1[kc*8 + q    ], QSC);
            qa[kc][2] = scale_pack(Qw0[kc*8 + q + 4], QSC);
            qa[kc][3] = scale_pack(Qw1[kc*8 + q + 4], QSC);
        }
    }

    float o[8][4];
    #pragma unroll
    for (int nc = 0; nc < 8; nc++)
        #pragma unroll
        for (int e = 0; e < 4; e++) o[nc][e] = 0.f;
    float mA = -1e30f, mB = -1e30f, lA = 0.f, lB = 0.f;

    for (int kt = 0; kt < ntiles; kt += 2) {
        CP_WAIT2();
        __syncthreads();
        #pragma unroll
        for (int pp = 0; pp < 2; pp++) {
            int t = kt + 4 + pp;
            if (t < ntiles) {
                int st = t % 6;
                __nv_bfloat16* Kb = smh + st*STAGEH;
                __nv_bfloat16* Vb = Kb + 64*KS_LDH;
                #pragma unroll
                for (int i = 0; i < 2; i++) {
                    int idx = tid + i*256;
                    int r = idx >> 3, seg = (idx & 7) * 8;
                    cp16h(Kb + r*KS_LDH + seg, qk + ((size_t)(b*Tv + t*64 + r))*(2*Dv) + Dv + h*HDv + seg);
                    cp16h(Vb + r*KS_LDH + seg, vT + ((size_t)(h*HDv + r))*Mrows + b*Tv + t*64 + seg);
                }
            }
            CP_COMMIT();
        }

        #pragma unroll
        for (int sub = 0; sub < 2; sub++) {
            const int kti = kt + sub;
            const int kbase = kti*64;
            const uint32_t kst = smbase + (uint32_t)(((kti % 6)*STAGEH) * 2);
            const uint32_t vst = kst + (uint32_t)(64*KS_LDH*2);

            float s[8][4];
            #pragma unroll
            for (int nc = 0; nc < 8; nc++) {
                s[nc][0] = 0.f; s[nc][1] = 0.f; s[nc][2] = 0.f; s[nc][3] = 0.f;
            }
            #pragma unroll
            for (int ncp = 0; ncp < 4; ncp++) {
                #pragma unroll
                for (int kc = 0; kc < 4; kc++) {
                    uint32_t b0, b1, b2, b3;
                    ldsm4(b0, b1, b2, b3, kst + bOff + (uint32_t)(((ncp*16)*KS_LDH + kc*16) * 2));
                    mma_bf16(s[2*ncp][0], s[2*ncp][1], s[2*ncp][2], s[2*ncp][3],
                             qa[kc][0], qa[kc][1], qa[kc][2], qa[kc][3], b0, b1);
                    mma_bf16(s[2*ncp+1][0], s[2*ncp+1][1], s[2*ncp+1][2], s[2*ncp+1][3],
                             qa[kc][0], qa[kc][1], qa[kc][2], qa[kc][3], b2, b3);
                }
            }

            if (kbase + 63 > qrow0) {
                int rowA = qrow0 + g, rowB = qrow0 + g + 8;
                #pragma unroll
                for (int nc = 0; nc < 8; nc++) {
                    int c0 = kbase + nc*8 + 2*q, c1 = c0 + 1;
                    if (c0 > rowA) s[nc][0] = -1e30f;
                    if (c1 > rowA) s[nc][1] = -1e30f;
                    if (c0 > rowB) s[nc][2] = -1e30f;
                    if (c1 > rowB) s[nc][3] = -1e30f;
                }
            }

            float rmA = -1e30f, rmB = -1e30f;
            #pragma unroll
            for (int nc = 0; nc < 8; nc++) {
                rmA = fmaxf(rmA, fmaxf(s[nc][0], s[nc][1]));
                rmB = fmaxf(rmB, fmaxf(s[nc][2], s[nc][3]));
            }
            rmA = fmaxf(rmA, __shfl_xor_sync(0xffffffffu, rmA, 1));
            rmA = fmaxf(rmA, __shfl_xor_sync(0xffffffffu, rmA, 2));
            rmB = fmaxf(rmB, __shfl_xor_sync(0xffffffffu, rmB, 1));
            rmB = fmaxf(rmB, __shfl_xor_sync(0xffffffffu, rmB, 2));
            float mnA = fmaxf(mA, rmA), mnB = fmaxf(mB, rmB);
            float corrA = ex2(mA - mnA), corrB = ex2(mB - mnB);
            mA = mnA; mB = mnB;

            uint32_t pa[4][4];
            #pragma unroll
            for (int kc = 0; kc < 4; kc++) {
                pa[kc][0] = ex2b2(packbf(s[2*kc][0]   - mnA, s[2*kc][1]   - mnA));
                pa[kc][1] = ex2b2(packbf(s[2*kc][2]   - mnB, s[2*kc][3]   - mnB));
                pa[kc][2] = ex2b2(packbf(s[2*kc+1][0] - mnA, s[2*kc+1][1] - mnA));
                pa[kc][3] = ex2b2(packbf(s[2*kc+1][2] - mnB, s[2*kc+1][3] - mnB));
            }

            #pragma unroll
            for (int nc = 0; nc < 8; nc++) {
                o[nc][0] *= corrA; o[nc][1] *= corrA;
                o[nc][2] *= corrB; o[nc][3] *= corrB;
            }
            #pragma unroll
            for (int ncp = 0; ncp < 4; ncp++) {
                #pragma unroll
                for (int kc = 0; kc < 4; kc++) {
                    uint32_t v0, v1, v2, v3;
                    ldsm4(v0, v1, v2, v3, vst + bOff + (uint32_t)(((ncp*16)*KS_LDH + kc*16) * 2));
                    mma_bf16(o[2*ncp][0], o[2*ncp][1], o[2*ncp][2], o[2*ncp][3],
                             pa[kc][0], pa[kc][1], pa[kc][2], pa[kc][3], v0, v1);
                    mma_bf16(o[2*ncp+1][0], o[2*ncp+1][1], o[2*ncp+1][2], o[2*ncp+1][3],
                             pa[kc][0], pa[kc][1], pa[kc][2], pa[kc][3], v2, v3);
                }
            }

            float rsA = 0.f, rsB = 0.f;
            #pragma unroll
            for (int kc = 0; kc < 4; kc++) {
                rsA += bf2sum(pa[kc][0]) + bf2sum(pa[kc][2]);
                rsB += bf2sum(pa[kc][1]) + bf2sum(pa[kc][3]);
            }
            rsA += __shfl_xor_sync(0xffffffffu, rsA, 1);
            rsA += __shfl_xor_sync(0xffffffffu, rsA, 2);
            rsB += __shfl_xor_sync(0xffffffffu, rsB, 1);
            rsB += __shfl_xor_sync(0xffffffffu, rsB, 2);
            lA = lA*corrA + rsA;
            lB = lB*corrB + rsB;
        }
    }

    float invA = 1.f / lA, invB = 1.f / lB;
    __nv_bfloat16* ob0 = out + ((size_t)(b*Tv + qrow0 + g    ))*Dv + h*HDv;
    __nv_bfloat16* ob1 = out + ((size_t)(b*Tv + qrow0 + g + 8))*Dv + h*HDv;
    #pragma unroll
    for (int nc = 0; nc < 8; nc++) {
        int c = nc*8 + 2*q;
        *(uint32_t*)&ob0[c] = packbf(o[nc][0]*invA, o[nc][1]*invA);
        *(uint32_t*)&ob1[c] = packbf(o[nc][2]*invB, o[nc][3]*invB);
    }
}

// ---------------- Parallel selective scan (CH=64) ----------------
__global__ __launch_bounds__(256) void scan_phase1(
    const float* __restrict__ dt, const float* __restrict__ z,
    const float* __restrict__ Bi, const float* __restrict__ A_log)
{
    int gth = blockIdx.x*256 + threadIdx.x;
    int chan = gth & 127, chunk = gth >> 7;
    int b = chan >> 6, sc = chan & 63;
    float A[16];
    #pragma unroll
    for (int st = 0; st < 16; st++) A[st] = -__expf(A_log[sc*STv + st]);
    float aP[16], bP[16];
    #pragma unroll
    for (int st = 0; st < 16; st++) { aP[st] = 1.f; bP[st] = 0.f; }
    int t0 = chunk*TSTEP;
    const float* dtp = dt + ((size_t)b*Tv + t0)*SCv + sc;
    const float* zp  = z  + ((size_t)b*Tv + t0)*SCv + sc;
    const float* Bp  = Bi + ((size_t)b*Tv + t0)*STv;
    for (int tt = 0; tt < TSTEP; tt++) {
        float dtc = dtp[(size_t)tt*SCv];
        float zc  = zp [(size_t)tt*SCv];
        float dz  = dtc*zc;
        float4 B0 = *(const float4*)&Bp[tt*STv + 0];
        float4 B1 = *(const float4*)&Bp[tt*STv + 4];
        float4 B2 = *(const float4*)&Bp[tt*STv + 8];
        float4 B3 = *(const float4*)&Bp[tt*STv + 12];
        float Bvv[16] = {B0.x,B0.y,B0.z,B0.w, B1.x,B1.y,B1.z,B1.w,
                         B2.x,B2.y,B2.z,B2.w, B3.x,B3.y,B3.z,B3.w};
        #pragma unroll
        for (int st = 0; st < 16; st++) {
            float ab = fmaf(dtc, A[st], 1.f);
            aP[st] *= ab;
            bP[st] = fmaf(ab, bP[st], dz*Bvv[st]);
        }
    }
    int base = (chan*CH + chunk)*16;
    #pragma unroll
    for (int st = 0; st < 16; st++) { g_scanA[base+st] = aP[st]; g_scanB[base+st] = bP[st]; }
}

__global__ __launch_bounds__(256) void scan_phase2()
{
    int gth = blockIdx.x*256 + threadIdx.x;
    int chan = gth >> 4, st = gth & 15;
    int base = chan*CH*16 + st;
    float s = 0.f;
    float a = g_scanA[base], bq = g_scanB[base];
    #pragma unroll 8
    for (int ch = 0; ch < CH; ch++) {
        int idx = base + ch*16;
        float an = 0.f, bn = 0.f;
        if (ch + 1 < CH) { an = g_scanA[idx + 16]; bn = g_scanB[idx + 16]; }
        g_scanS[idx] = s;
        s = fmaf(a, s, bq);
        a = an; bq = bn;
    }
}

__global__ __launch_bounds__(256) void scan_phase3(
    const float* __restrict__ dt, const float* __restrict__ z,
    const float* __restrict__ Bi, const float* __restrict__ Ci,
    const float* __restrict__ gate, const float* __restrict__ A_log,
    __nv_bfloat16* __restrict__ y)
{
    int gth = blockIdx.x*256 + threadIdx.x;
    int chan = gth & 127, chunk = gth >> 7;
    int b = chan >> 6, sc = chan & 63;
    float A[16];
    #pragma unroll
    for (int st = 0; st < 16; st++) A[st] = -__expf(A_log[sc*STv + st]);
    float state[16];
    {
        int base = (chan*CH + chunk)*16;
        #pragma unroll
        for (int st = 0; st < 16; st++) state[st] = g_scanS[base+st];
    }
    int t0 = chunk*TSTEP;
    const float* dtp = dt   + ((size_t)b*Tv + t0)*SCv + sc;
    const float* zp  = z    + ((size_t)b*Tv + t0)*SCv + sc;
    const float* gp  = gate + ((size_t)b*Tv + t0)*SCv + sc;
    const float* Bp  = Bi + ((size_t)b*Tv + t0)*STv;
    const float* Cp  = Ci + ((size_t)b*Tv + t0)*STv;
    __nv_bfloat16* yp = y + ((size_t)b*Tv + t0)*SCv + sc;
    for (int tt = 0; tt < TSTEP; tt++) {
        float dtc = dtp[(size_t)tt*SCv];
        float zc  = zp [(size_t)tt*SCv];
        float dz  = dtc*zc;
        float4 B0 = *(const float4*)&Bp[tt*STv + 0];
        float4 B1 = *(const float4*)&Bp[tt*STv + 4];
        float4 B2 = *(const float4*)&Bp[tt*STv + 8];
        float4 B3 = *(const float4*)&Bp[tt*STv + 12];
        float4 C0 = *(const float4*)&Cp[tt*STv + 0];
        float4 C1 = *(const float4*)&Cp[tt*STv + 4];
        float4 C2 = *(const float4*)&Cp[tt*STv + 8];
        float4 C3 = *(const float4*)&Cp[tt*STv + 12];
        float Bvv[16] = {B0.x,B0.y,B0.z,B0.w, B1.x,B1.y,B1.z,B1.w,
                         B2.x,B2.y,B2.z,B2.w, B3.x,B3.y,B3.z,B3.w};
        float Cvv[16] = {C0.x,C0.y,C0.z,C0.w, C1.x,C1.y,C1.z,C1.w,
                         C2.x,C2.y,C2.z,C2.w, C3.x,C3.y,C3.z,C3.w};
        float p0 = 0.f, p1 = 0.f, p2 = 0.f, p3 = 0.f;
        #pragma unroll
        for (int st = 0; st < 16; st += 4) {
            float ab;
            ab = fmaf(dtc, A[st+0], 1.f); state[st+0] = fmaf(ab, state[st+0], dz*Bvv[st+0]); p0 = fmaf(state[st+0], Cvv[st+0], p0);
            ab = fmaf(dtc, A[st+1], 1.f); state[st+1] = fmaf(ab, state[st+1], dz*Bvv[st+1]); p1 = fmaf(state[st+1], Cvv[st+1], p1);
            ab = fmaf(dtc, A[st+2], 1.f); state[st+2] = fmaf(ab, state[st+2], dz*Bvv[st+2]); p2 = fmaf(state[st+2], Cvv[st+2], p2);
            ab = fmaf(dtc, A[st+3], 1.f); state[st+3] = fmaf(ab, state[st+3], dz*Bvv[st+3]); p3 = fmaf(state[st+3], Cvv[st+3], p3);
        }
        float p = (p0 + p1) + (p2 + p3);
        yp[(size_t)tt*SCv] = __float2bfloat16(p * gp[(size_t)tt*SCv]);
    }
}

// ---------------- launch ----------------
extern "C" void kernel_launch(void* const* d_in, const int* in_sizes, int n_in,
                              void* d_out, int out_size)
{
    const float* x      = (const float*)d_in[0];
    const float* qkv_w  = (const float*)d_in[1];
    const float* o_w    = (const float*)d_in[2];
    const float* n1w    = (const float*)d_in[3];
    const float* n2w    = (const float*)d_in[4];
    const float* in_w   = (const float*)d_in[5];
    const float* out_w  = (const float*)d_in[6];
    const float* A_log  = (const float*)d_in[7];
    const float* Bp_w   = (const float*)d_in[8];
    const float* Cp_w   = (const float*)d_in[9];
    const float* dt_w   = (const float*)d_in[10];
    const float* dt_b   = (const float*)d_in[11];
    const float* gate_w = (const float*)d_in[12];
    float* out = (float*)d_out;

    __nv_bfloat16 *hb,*qkb,*vTb,*attnb,*h2b,*yb16,*wq,*wo,*wzg,*wout;
    float *x1,*zb,*gateb,*Bib,*Cib,*dtb,*zgacc;
    cudaGetSymbolAddress((void**)&hb,   g_h);
    cudaGetSymbolAddress((void**)&qkb,  g_qk);
    cudaGetSymbolAddress((void**)&vTb,  g_vT);
    cudaGetSymbolAddress((void**)&attnb,g_attn);
    cudaGetSymbolAddress((void**)&x1,   g_x1);
    cudaGetSymbolAddress((void**)&h2b,  g_h2);
    cudaGetSymbolAddress((void**)&zb,   g_z);
    cudaGetSymbolAddress((void**)&gateb,g_gate);
    cudaGetSymbolAddress((void**)&Bib,  g_Bi);
    cudaGetSymbolAddress((void**)&Cib,  g_Ci);
    cudaGetSymbolAddress((void**)&dtb,  g_dt);
    cudaGetSymbolAddress((void**)&yb16, g_y);
    cudaGetSymbolAddress((void**)&zgacc,g_zgacc);
    cudaGetSymbolAddress((void**)&wq,   g_wq);
    cudaGetSymbolAddress((void**)&wo,   g_wo);
    cudaGetSymbolAddress((void**)&wzg,  g_wzg);
    cudaGetSymbolAddress((void**)&wout, g_wout);

    const int gemm_smem = 6*GSTG*2;     // 110592 B
    const int attn_smem = 6*STAGEH*2;   // 110592 B
    cudaFuncSetAttribute(gemm_bf16, cudaFuncAttributeMaxDynamicSharedMemorySize, gemm_smem);
    cudaFuncSetAttribute(attn_mma_kernel, cudaFuncAttributeMaxDynamicSharedMemorySize, attn_smem);

    // 0. fused rmsnorm1 + weight convert
    conv_norm<<<Mrows + CONVBLKS, 256>>>(x, n1w, hb, qkv_w, o_w, in_w, gate_w, out_w);
    // 1. qkv: Q,K -> g_qk (bf16), V -> g_vT (transposed bf16)
    gemm_bf16<<<dim3(24, 32), 256, gemm_smem>>>(hb, wq, nullptr, qkb, vTb,
                                     Mrows, 3*Dv, 2*Dv, Dv, Dv, 2, 3, 2*Dv, 0);
    // 2. attention -> bf16
    attn_mma_kernel<<<dim3(Tv/128, Hv, Bv), 256, attn_smem>>>(qkb, vTb, attnb);
    // 3. x1 = x + attn @ o_w^T (fp32)
    gemm_bf16<<<dim3(8, 32), 256, gemm_smem>>>(attnb, wo, x, x1, nullptr,
                                    Mrows, Dv, Dv, Dv, Dv, 1, 1, Dv, 0);
    // 4. rmsnorm2 -> bf16
    rmsnorm_kernel<<<Mrows, 256>>>(x1, n2w, h2b);
    // 5. z/gate split-K (4 splits of K=256) -> partials
    gemm_bf16<<<dim3(1, 32, ZSPLIT), 256, gemm_smem>>>(h2b, wzg, nullptr, zgacc, nullptr,
                                    Mrows, 2*SCv, 2*SCv, Dv/ZSPLIT, Dv, 0, 0, 2*SCv, 0);
    // 6. fused reduce + Bi/Ci/dt (256 CTAs)
    bcd_fused<<<256, 256>>>(Bp_w, Cp_w, dt_w, dt_b, zb, gateb, Bib, Cib, dtb);
    // 7. parallel scan -> y bf16
    scan_phase1<<<32, 256>>>(dtb, zb, Bib, A_log);
    scan_phase2<<<8, 256>>>();
    scan_phase3<<<32, 256>>>(dtb, zb, Bib, Cib, gateb, A_log, yb16);
    // 8. out = x1 + y @ out_w^T (fp32)
    gemm_bf16<<<dim3(8, 32), 256, gemm_smem>>>(yb16, wout, x1, out, nullptr,
                                    Mrows, Dv, Dv, SCv, SCv, 1, 1, Dv, 0);
}